// round 1
// baseline (speedup 1.0000x reference)
#include <cuda_runtime.h>
#include <math.h>

#define HW    57600
#define IMGW  240
#define LOG_MAX 4.6051701859880914f  // log(1/0.01)

// Scratch (allocation-free):
__device__ float g_conv1[288 * HW];  // [0:192)=xp (conv_in), [192:288)=fp (conv_f)
__device__ float g_y[96 * HW];       // concat of 3 attention branch outputs
__device__ float g_v1[32 * HW];      // row-attention intermediate for branch 2

// ---------------------------------------------------------------------------
// Direct 3x3 conv, Cin=96 fixed, pad=1. Block (32,8); tile 32x32; 8 OC/block;
// each thread: 1 column x 4 rows x 8 OC. All weights for this OC group in smem.
// ---------------------------------------------------------------------------
__global__ __launch_bounds__(256) void conv3x3_kernel(
    const float* __restrict__ in, const float* __restrict__ wt,
    const float* __restrict__ bias, float* __restrict__ out) {
    __shared__ float s_w[96 * 72];       // [ic][oc][9]
    __shared__ float s_in[34 * 34];
    const int tx = threadIdx.x, ty = threadIdx.y;
    const int tid = ty * 32 + tx;
    const int x0 = blockIdx.x * 32, y0 = blockIdx.y * 32;
    const int oc0 = blockIdx.z * 8;

    for (int idx = tid; idx < 96 * 72; idx += 256) {
        int ic = idx / 72, rem = idx % 72;
        int o = rem / 9, k = rem % 9;
        s_w[idx] = wt[((oc0 + o) * 96 + ic) * 9 + k];
    }

    float acc[8][4];
#pragma unroll
    for (int o = 0; o < 8; o++) {
        float b = bias[oc0 + o];
#pragma unroll
        for (int r = 0; r < 4; r++) acc[o][r] = b;
    }

    for (int ic = 0; ic < 96; ic++) {
        const float* ip = in + ic * HW;
        __syncthreads();  // protect s_in from previous iter (and s_w preload on iter 0)
        for (int idx = tid; idx < 34 * 34; idx += 256) {
            int ly = idx / 34, lx = idx % 34;
            int gy = y0 - 1 + ly, gx = x0 - 1 + lx;
            s_in[idx] = (gy >= 0 && gy < IMGW && gx >= 0 && gx < IMGW)
                            ? ip[gy * IMGW + gx] : 0.f;
        }
        __syncthreads();

        float r[6][3];
#pragma unroll
        for (int u = 0; u < 6; u++)
#pragma unroll
            for (int v = 0; v < 3; v++)
                r[u][v] = s_in[(4 * ty + u) * 34 + tx + v];

        const float* wp = &s_w[ic * 72];
#pragma unroll
        for (int o = 0; o < 8; o++) {
#pragma unroll
            for (int ky = 0; ky < 3; ky++)
#pragma unroll
                for (int kx = 0; kx < 3; kx++) {
                    float wv = wp[o * 9 + ky * 3 + kx];
#pragma unroll
                    for (int ry = 0; ry < 4; ry++)
                        acc[o][ry] = fmaf(r[ry + ky][kx], wv, acc[o][ry]);
                }
        }
    }

    const int gx = x0 + tx;
    if (gx < IMGW) {
#pragma unroll
        for (int o = 0; o < 8; o++)
#pragma unroll
            for (int ry = 0; ry < 4; ry++) {
                int gy = y0 + 4 * ty + ry;
                if (gy < IMGW)
                    out[(oc0 + o) * HW + gy * IMGW + gx] = acc[o][ry];
            }
    }
}

__device__ __forceinline__ float4 l2n(float4 a) {
    float n = sqrtf(a.x * a.x + a.y * a.y + a.z * a.z + a.w * a.w);
    float inv = 1.f / fmaxf(n, 1e-12f);
    a.x *= inv; a.y *= inv; a.z *= inv; a.w *= inv;
    return a;
}

// ---------------------------------------------------------------------------
// Window attention (branches 0 and 1). One block per (window, branch).
// Threads 0..199 = (head n in 0..7, token in 0..24). hd=4 -> float4.
// Branch 1: read rolled by +3 (roll(-3)), write rolled by +2 (roll(+2)).
// ---------------------------------------------------------------------------
__global__ __launch_bounds__(256) void win_attn_kernel(const float* __restrict__ ls) {
    const int branch = blockIdx.y;
    const int win = blockIdx.x;
    const int Hw = win / 48, Ww = win % 48;
    const int t = threadIdx.x;

    __shared__ float4 s_k[8][25];
    __shared__ float4 s_v[8][25];
    __shared__ float s_sc[8];

    if (t < 8) s_sc[t] = expf(fminf(ls[t], LOG_MAX));

    const int n = t / 25, tok = t % 25;
    const int wy = tok / 5, wx = tok % 5;
    const int py = Hw * 5 + wy, px = Ww * 5 + wx;  // logical window pixel
    int gy = py, gx = px;                           // source pixel (rolled input)
    if (branch) { gy = (gy + 3) % IMGW; gx = (gx + 3) % IMGW; }
    const int pos = gy * IMGW + gx;

    if (t < 200) {
        const float* xb = g_conv1 + branch * 64 * HW;  // xs[branch], 64 ch
        float4 kk, vv;
        kk.x = xb[(n * 4 + 0) * HW + pos];
        kk.y = xb[(n * 4 + 1) * HW + pos];
        kk.z = xb[(n * 4 + 2) * HW + pos];
        kk.w = xb[(n * 4 + 3) * HW + pos];
        vv.x = xb[(32 + n * 4 + 0) * HW + pos];
        vv.y = xb[(32 + n * 4 + 1) * HW + pos];
        vv.z = xb[(32 + n * 4 + 2) * HW + pos];
        vv.w = xb[(32 + n * 4 + 3) * HW + pos];
        s_k[n][tok] = l2n(kk);
        s_v[n][tok] = vv;
    }
    __syncthreads();
    if (t >= 200) return;

    const float* fb = g_conv1 + (192 + branch * 32) * HW;  // fs[branch], 32 ch
    float4 q;
    q.x = fb[(n * 4 + 0) * HW + pos];
    q.y = fb[(n * 4 + 1) * HW + pos];
    q.z = fb[(n * 4 + 2) * HW + pos];
    q.w = fb[(n * 4 + 3) * HW + pos];
    q = l2n(q);
    const float sc = s_sc[n];

    float m = -1e30f, l = 0.f;
    float ax = 0, ay = 0, az = 0, aw = 0;
#pragma unroll
    for (int j = 0; j < 25; j++) {
        float4 kj = s_k[n][j];
        float s = sc * (q.x * kj.x + q.y * kj.y + q.z * kj.z + q.w * kj.w);
        float mn = fmaxf(m, s);
        float corr = __expf(m - mn);
        float w = __expf(s - mn);
        float4 vj = s_v[n][j];
        l = l * corr + w;
        ax = ax * corr + w * vj.x;
        ay = ay * corr + w * vj.y;
        az = az * corr + w * vj.z;
        aw = aw * corr + w * vj.w;
        m = mn;
    }
    float invl = 1.f / l;

    int oy = py, ox = px;
    if (branch) { oy = (oy + 2) % IMGW; ox = (ox + 2) % IMGW; }
    const int opos = oy * IMGW + ox;
    float* yb = g_y + branch * 32 * HW;
    yb[(n * 4 + 0) * HW + opos] = ax * invl;
    yb[(n * 4 + 1) * HW + opos] = ay * invl;
    yb[(n * 4 + 2) * HW + opos] = az * invl;
    yb[(n * 4 + 3) * HW + opos] = aw * invl;
}

// ---------------------------------------------------------------------------
// Branch 2, pass 1: row attention. One block per (head n, row h).
// xs[2]: conv1 ch 128..191 (k=128+, v=160+), fs[2]: conv1 ch 256..287.
// ---------------------------------------------------------------------------
__global__ __launch_bounds__(256) void axial_row_kernel(const float* __restrict__ lrls) {
    const int n = blockIdx.x / IMGW, h = blockIdx.x % IMGW;
    const int t = threadIdx.x;
    __shared__ float4 s_k[240], s_v[240];
    __shared__ float s_sc;
    if (t == 0) s_sc = expf(fminf(lrls[n], LOG_MAX));

    if (t < 240) {
        const int pos = h * IMGW + t;
        float4 kk, vv;
        kk.x = g_conv1[(128 + n * 4 + 0) * HW + pos];
        kk.y = g_conv1[(128 + n * 4 + 1) * HW + pos];
        kk.z = g_conv1[(128 + n * 4 + 2) * HW + pos];
        kk.w = g_conv1[(128 + n * 4 + 3) * HW + pos];
        vv.x = g_conv1[(160 + n * 4 + 0) * HW + pos];
        vv.y = g_conv1[(160 + n * 4 + 1) * HW + pos];
        vv.z = g_conv1[(160 + n * 4 + 2) * HW + pos];
        vv.w = g_conv1[(160 + n * 4 + 3) * HW + pos];
        s_k[t] = l2n(kk);
        s_v[t] = vv;
    }
    __syncthreads();
    if (t >= 240) return;

    const int pos = h * IMGW + t;
    float4 q;
    q.x = g_conv1[(256 + n * 4 + 0) * HW + pos];
    q.y = g_conv1[(256 + n * 4 + 1) * HW + pos];
    q.z = g_conv1[(256 + n * 4 + 2) * HW + pos];
    q.w = g_conv1[(256 + n * 4 + 3) * HW + pos];
    q = l2n(q);
    const float sc = s_sc;

    float m = -1e30f, l = 0.f;
    float ax = 0, ay = 0, az = 0, aw = 0;
    for (int j = 0; j < 240; j++) {
        float4 kj = s_k[j];
        float s = sc * (q.x * kj.x + q.y * kj.y + q.z * kj.z + q.w * kj.w);
        float mn = fmaxf(m, s);
        float corr = __expf(m - mn);
        float w = __expf(s - mn);
        float4 vj = s_v[j];
        l = l * corr + w;
        ax = ax * corr + w * vj.x;
        ay = ay * corr + w * vj.y;
        az = az * corr + w * vj.z;
        aw = aw * corr + w * vj.w;
        m = mn;
    }
    float invl = 1.f / l;
    g_v1[(n * 4 + 0) * HW + pos] = ax * invl;
    g_v1[(n * 4 + 1) * HW + pos] = ay * invl;
    g_v1[(n * 4 + 2) * HW + pos] = az * invl;
    g_v1[(n * 4 + 3) * HW + pos] = aw * invl;
}

// ---------------------------------------------------------------------------
// Branch 2, pass 2: column attention. One block per (head n, column w).
// q/k re-derived (normalized) from conv1; v comes from g_v1 (row-attended).
// Output -> g_y channels 64 + n*4 + d.
// ---------------------------------------------------------------------------
__global__ __launch_bounds__(256) void axial_col_kernel(const float* __restrict__ lrls) {
    const int n = blockIdx.x / IMGW, w = blockIdx.x % IMGW;
    const int t = threadIdx.x;
    __shared__ float4 s_k[240], s_v[240];
    __shared__ float s_sc;
    if (t == 0) s_sc = expf(fminf(lrls[n], LOG_MAX));

    if (t < 240) {
        const int pos = t * IMGW + w;  // row t, column w
        float4 kk, vv;
        kk.x = g_conv1[(128 + n * 4 + 0) * HW + pos];
        kk.y = g_conv1[(128 + n * 4 + 1) * HW + pos];
        kk.z = g_conv1[(128 + n * 4 + 2) * HW + pos];
        kk.w = g_conv1[(128 + n * 4 + 3) * HW + pos];
        vv.x = g_v1[(n * 4 + 0) * HW + pos];
        vv.y = g_v1[(n * 4 + 1) * HW + pos];
        vv.z = g_v1[(n * 4 + 2) * HW + pos];
        vv.w = g_v1[(n * 4 + 3) * HW + pos];
        s_k[t] = l2n(kk);
        s_v[t] = vv;
    }
    __syncthreads();
    if (t >= 240) return;

    const int pos = t * IMGW + w;
    float4 q;
    q.x = g_conv1[(256 + n * 4 + 0) * HW + pos];
    q.y = g_conv1[(256 + n * 4 + 1) * HW + pos];
    q.z = g_conv1[(256 + n * 4 + 2) * HW + pos];
    q.w = g_conv1[(256 + n * 4 + 3) * HW + pos];
    q = l2n(q);
    const float sc = s_sc;

    float m = -1e30f, l = 0.f;
    float ax = 0, ay = 0, az = 0, aw = 0;
    for (int j = 0; j < 240; j++) {
        float4 kj = s_k[j];
        float s = sc * (q.x * kj.x + q.y * kj.y + q.z * kj.z + q.w * kj.w);
        float mn = fmaxf(m, s);
        float corr = __expf(m - mn);
        float wgt = __expf(s - mn);
        float4 vj = s_v[j];
        l = l * corr + wgt;
        ax = ax * corr + wgt * vj.x;
        ay = ay * corr + wgt * vj.y;
        az = az * corr + wgt * vj.z;
        aw = aw * corr + wgt * vj.w;
        m = mn;
    }
    float invl = 1.f / l;
    g_y[(64 + n * 4 + 0) * HW + pos] = ax * invl;
    g_y[(64 + n * 4 + 1) * HW + pos] = ay * invl;
    g_y[(64 + n * 4 + 2) * HW + pos] = az * invl;
    g_y[(64 + n * 4 + 3) * HW + pos] = aw * invl;
}

// ---------------------------------------------------------------------------
extern "C" void kernel_launch(void* const* d_in, const int* in_sizes, int n_in,
                              void* d_out, int out_size) {
    const float* x      = (const float*)d_in[0];
    const float* w_in   = (const float*)d_in[1];
    const float* b_in   = (const float*)d_in[2];
    const float* w_f    = (const float*)d_in[3];
    const float* b_f    = (const float*)d_in[4];
    const float* w_out  = (const float*)d_in[5];
    const float* b_out  = (const float*)d_in[6];
    const float* ls     = (const float*)d_in[7];
    const float* lr_ls  = (const float*)d_in[8];
    float* out = (float*)d_out;

    float* p_conv1; float* p_y;
    cudaGetSymbolAddress((void**)&p_conv1, g_conv1);
    cudaGetSymbolAddress((void**)&p_y, g_y);

    dim3 blk(32, 8);
    // conv_in: 96 -> 192 into conv1[0:192)
    conv3x3_kernel<<<dim3(8, 8, 24), blk>>>(x, w_in, b_in, p_conv1);
    // conv_f: 96 -> 96 into conv1[192:288)
    conv3x3_kernel<<<dim3(8, 8, 12), blk>>>(x, w_f, b_f, p_conv1 + 192 * HW);

    // window attention, branches 0 (plain) and 1 (shifted)
    win_attn_kernel<<<dim3(2304, 2), 256>>>(ls);

    // branch 2: axial row then column
    axial_row_kernel<<<8 * IMGW, 256>>>(lr_ls);
    axial_col_kernel<<<8 * IMGW, 256>>>(lr_ls);

    // output conv: 96 -> 96
    conv3x3_kernel<<<dim3(8, 8, 12), blk>>>(p_y, w_out, b_out, out);
}

// round 3
// speedup vs baseline: 1.0581x; 1.0581x over previous
#include <cuda_runtime.h>
#include <math.h>

#define HW    57600
#define IMGW  240
#define LOG_MAX 4.6051701859880914f  // log(1/0.01)

// Scratch (allocation-free):
__device__ float g_conv1[288 * HW];   // [0:192)=xp (conv_in), [192:288)=fp (conv_f)
__device__ float g_y[96 * HW];        // concat of 3 attention branch outputs
__device__ float g_v1[32 * HW];       // row-attention intermediate for branch 2
__device__ float g_wrep[768 * 864];   // repacked tf32 hi|lo weights (in|f|out)

__device__ __forceinline__ unsigned f2tf(float f) {
    unsigned r;
    asm("cvt.rna.tf32.f32 %0, %1;" : "=r"(r) : "f"(f));
    return r;
}

// ---------------------------------------------------------------------------
// Repack OIHW weights -> [chunk(ic/8)][shift(9)][ic_lo(8)][oc], tf32 hi + lo.
// wrep layout per tensor: [hi (Cout*864)][lo (Cout*864)].
// ---------------------------------------------------------------------------
__global__ void repack_w_kernel(const float* __restrict__ wt,
                                float* __restrict__ wrep, int Cout) {
    int idx = blockIdx.x * 256 + threadIdx.x;
    int total = Cout * 96 * 9;
    if (idx >= total) return;
    int o = idx % Cout;
    int rem = idx / Cout;
    int icl = rem % 8; rem /= 8;
    int s = rem % 9;
    int ch = rem / 9;
    int ic = ch * 8 + icl;
    float v = wt[(o * 96 + ic) * 9 + s];
    unsigned hi = f2tf(v);
    float res = v - __uint_as_float(hi);
    wrep[idx] = __uint_as_float(hi);
    wrep[total + idx] = __uint_as_float(f2tf(res));
}

// ---------------------------------------------------------------------------
// Implicit-GEMM 3x3 conv via mma.sync.m16n8k8 tf32, 3xTF32 decomposition.
// Block tile: 8x16 pixels (M=128) x 96 oc (N=96); 8 warps (wm 0..1, wn 0..3).
// Dynamic smem layout (unsigned words):
//   [0,1600)        A hi  [ic8][y10][x20]
//   [1600,3200)     A lo
//   [3200,10688)    B hi  [72][104]
//   [10688,18176)   B lo
// ---------------------------------------------------------------------------
__global__ __launch_bounds__(256) void conv3x3_mma_kernel(
    const float* __restrict__ in, const float* __restrict__ wrep,
    const float* __restrict__ bias, float* __restrict__ out, int Cout) {
    extern __shared__ unsigned smem[];
    unsigned* s_a_hi = smem;
    unsigned* s_a_lo = smem + 1600;
    unsigned* s_b_hi = smem + 3200;
    unsigned* s_b_lo = smem + 10688;

    const int tid = threadIdx.x;
    const int lane = tid & 31, w = tid >> 5;
    const int wm = w & 1, wn = w >> 1;
    const int x0 = blockIdx.x * 16, y0 = blockIdx.y * 8;
    const int oc_blk = blockIdx.z * 96;
    const int g = lane >> 2, t = lane & 3;  // groupID, threadID_in_group
    const int wlo = Cout * 864;             // lo-part offset in wrep

    float acc[4][3][4];
#pragma unroll
    for (int j = 0; j < 3; j++) {
        int oc = oc_blk + wn * 24 + j * 8 + 2 * t;
        float b0 = bias[oc], b1 = bias[oc + 1];
#pragma unroll
        for (int i = 0; i < 4; i++) {
            acc[i][j][0] = b0; acc[i][j][1] = b1;
            acc[i][j][2] = b0; acc[i][j][3] = b1;
        }
    }

    for (int ch = 0; ch < 12; ch++) {
        __syncthreads();
        // stage A halo: 8 ic x 10 x 18 with zero padding at borders (hi+lo)
        for (int idx = tid; idx < 8 * 10 * 18; idx += 256) {
            int ic = idx / 180, rem = idx % 180;
            int ly = rem / 18, lx = rem % 18;
            int gy = y0 - 1 + ly, gx = x0 - 1 + lx;
            float v = (gy >= 0 && gy < IMGW && gx >= 0 && gx < IMGW)
                          ? in[(ch * 8 + ic) * HW + gy * IMGW + gx] : 0.f;
            unsigned hi = f2tf(v);
            float res = v - __uint_as_float(hi);
            int off = ic * 200 + ly * 20 + lx;
            s_a_hi[off] = hi;
            s_a_lo[off] = f2tf(res);
        }
        // stage B: 72 rows x 96 oc, vectorized (tf32 bits already), hi+lo
        for (int idx = tid; idx < 72 * 24; idx += 256) {
            int r = idx / 24, c = idx % 24;
            const unsigned* src = (const unsigned*)wrep + (ch * 72 + r) * Cout + oc_blk + c * 4;
            *(uint4*)&s_b_hi[r * 104 + c * 4] = *(const uint4*)src;
            *(uint4*)&s_b_lo[r * 104 + c * 4] = *(const uint4*)(src + wlo);
        }
        __syncthreads();

#pragma unroll
        for (int s = 0; s < 9; s++) {
            const int dy = s / 3, dx = s % 3;  // halo idx: py+dy, px+dx (-1+1 cancels)
            unsigned bh[3][2], bl[3][2];
#pragma unroll
            for (int j = 0; j < 3; j++) {
                int oc = wn * 24 + j * 8 + g;
                bh[j][0] = s_b_hi[(s * 8 + t) * 104 + oc];
                bh[j][1] = s_b_hi[(s * 8 + t + 4) * 104 + oc];
                bl[j][0] = s_b_lo[(s * 8 + t) * 104 + oc];
                bl[j][1] = s_b_lo[(s * 8 + t + 4) * 104 + oc];
            }
#pragma unroll
            for (int i = 0; i < 4; i++) {
                int py = wm * 4 + i;
                int o00 = t * 200 + (py + dy) * 20 + g + dx;
                int o4  = o00 + 800;  // ic = t+4
                unsigned ah0 = s_a_hi[o00], ah1 = s_a_hi[o00 + 8];
                unsigned ah2 = s_a_hi[o4],  ah3 = s_a_hi[o4 + 8];
                unsigned al0 = s_a_lo[o00], al1 = s_a_lo[o00 + 8];
                unsigned al2 = s_a_lo[o4],  al3 = s_a_lo[o4 + 8];
#pragma unroll
                for (int j = 0; j < 3; j++) {
                    asm volatile(
                        "mma.sync.aligned.m16n8k8.row.col.f32.tf32.tf32.f32 "
                        "{%0,%1,%2,%3}, {%4,%5,%6,%7}, {%8,%9}, {%0,%1,%2,%3};"
                        : "+f"(acc[i][j][0]), "+f"(acc[i][j][1]),
                          "+f"(acc[i][j][2]), "+f"(acc[i][j][3])
                        : "r"(al0), "r"(al1), "r"(al2), "r"(al3),
                          "r"(bh[j][0]), "r"(bh[j][1]));
                    asm volatile(
                        "mma.sync.aligned.m16n8k8.row.col.f32.tf32.tf32.f32 "
                        "{%0,%1,%2,%3}, {%4,%5,%6,%7}, {%8,%9}, {%0,%1,%2,%3};"
                        : "+f"(acc[i][j][0]), "+f"(acc[i][j][1]),
                          "+f"(acc[i][j][2]), "+f"(acc[i][j][3])
                        : "r"(ah0), "r"(ah1), "r"(ah2), "r"(ah3),
                          "r"(bl[j][0]), "r"(bl[j][1]));
                    asm volatile(
                        "mma.sync.aligned.m16n8k8.row.col.f32.tf32.tf32.f32 "
                        "{%0,%1,%2,%3}, {%4,%5,%6,%7}, {%8,%9}, {%0,%1,%2,%3};"
                        : "+f"(acc[i][j][0]), "+f"(acc[i][j][1]),
                          "+f"(acc[i][j][2]), "+f"(acc[i][j][3])
                        : "r"(ah0), "r"(ah1), "r"(ah2), "r"(ah3),
                          "r"(bh[j][0]), "r"(bh[j][1]));
                }
            }
        }
    }

    // epilogue
    const int gx0 = x0 + g;
#pragma unroll
    for (int i = 0; i < 4; i++) {
        int gy = y0 + wm * 4 + i;
#pragma unroll
        for (int j = 0; j < 3; j++) {
            int oc = oc_blk + wn * 24 + j * 8 + 2 * t;
            out[oc * HW + gy * IMGW + gx0] = acc[i][j][0];
            out[(oc + 1) * HW + gy * IMGW + gx0] = acc[i][j][1];
            out[oc * HW + gy * IMGW + gx0 + 8] = acc[i][j][2];
            out[(oc + 1) * HW + gy * IMGW + gx0 + 8] = acc[i][j][3];
        }
    }
}

__device__ __forceinline__ float4 l2n(float4 a) {
    float n = sqrtf(a.x * a.x + a.y * a.y + a.z * a.z + a.w * a.w);
    float inv = 1.f / fmaxf(n, 1e-12f);
    a.x *= inv; a.y *= inv; a.z *= inv; a.w *= inv;
    return a;
}

// ---------------------------------------------------------------------------
// Window attention (branches 0 and 1). One block per (window, branch).
// ---------------------------------------------------------------------------
__global__ __launch_bounds__(256) void win_attn_kernel(const float* __restrict__ ls) {
    const int branch = blockIdx.y;
    const int win = blockIdx.x;
    const int Hw = win / 48, Ww = win % 48;
    const int t = threadIdx.x;

    __shared__ float4 s_k[8][25];
    __shared__ float4 s_v[8][25];
    __shared__ float s_sc[8];

    if (t < 8) s_sc[t] = expf(fminf(ls[t], LOG_MAX));

    const int n = t / 25, tok = t % 25;
    const int wy = tok / 5, wx = tok % 5;
    const int py = Hw * 5 + wy, px = Ww * 5 + wx;
    int gy = py, gx = px;
    if (branch) { gy = (gy + 3) % IMGW; gx = (gx + 3) % IMGW; }
    const int pos = gy * IMGW + gx;

    if (t < 200) {
        const float* xb = g_conv1 + branch * 64 * HW;
        float4 kk, vv;
        kk.x = xb[(n * 4 + 0) * HW + pos];
        kk.y = xb[(n * 4 + 1) * HW + pos];
        kk.z = xb[(n * 4 + 2) * HW + pos];
        kk.w = xb[(n * 4 + 3) * HW + pos];
        vv.x = xb[(32 + n * 4 + 0) * HW + pos];
        vv.y = xb[(32 + n * 4 + 1) * HW + pos];
        vv.z = xb[(32 + n * 4 + 2) * HW + pos];
        vv.w = xb[(32 + n * 4 + 3) * HW + pos];
        s_k[n][tok] = l2n(kk);
        s_v[n][tok] = vv;
    }
    __syncthreads();
    if (t >= 200) return;

    const float* fb = g_conv1 + (192 + branch * 32) * HW;
    float4 q;
    q.x = fb[(n * 4 + 0) * HW + pos];
    q.y = fb[(n * 4 + 1) * HW + pos];
    q.z = fb[(n * 4 + 2) * HW + pos];
    q.w = fb[(n * 4 + 3) * HW + pos];
    q = l2n(q);
    const float sc = s_sc[n];

    float m = -1e30f, l = 0.f;
    float ax = 0, ay = 0, az = 0, aw = 0;
#pragma unroll
    for (int j = 0; j < 25; j++) {
        float4 kj = s_k[n][j];
        float s = sc * (q.x * kj.x + q.y * kj.y + q.z * kj.z + q.w * kj.w);
        float mn = fmaxf(m, s);
        float corr = __expf(m - mn);
        float w = __expf(s - mn);
        float4 vj = s_v[n][j];
        l = l * corr + w;
        ax = ax * corr + w * vj.x;
        ay = ay * corr + w * vj.y;
        az = az * corr + w * vj.z;
        aw = aw * corr + w * vj.w;
        m = mn;
    }
    float invl = 1.f / l;

    int oy = py, ox = px;
    if (branch) { oy = (oy + 2) % IMGW; ox = (ox + 2) % IMGW; }
    const int opos = oy * IMGW + ox;
    float* yb = g_y + branch * 32 * HW;
    yb[(n * 4 + 0) * HW + opos] = ax * invl;
    yb[(n * 4 + 1) * HW + opos] = ay * invl;
    yb[(n * 4 + 2) * HW + opos] = az * invl;
    yb[(n * 4 + 3) * HW + opos] = aw * invl;
}

// ---------------------------------------------------------------------------
// Branch 2, pass 1: row attention.
// ---------------------------------------------------------------------------
__global__ __launch_bounds__(256) void axial_row_kernel(const float* __restrict__ lrls) {
    const int n = blockIdx.x / IMGW, h = blockIdx.x % IMGW;
    const int t = threadIdx.x;
    __shared__ float4 s_k[240], s_v[240];
    __shared__ float s_sc;
    if (t == 0) s_sc = expf(fminf(lrls[n], LOG_MAX));

    if (t < 240) {
        const int pos = h * IMGW + t;
        float4 kk, vv;
        kk.x = g_conv1[(128 + n * 4 + 0) * HW + pos];
        kk.y = g_conv1[(128 + n * 4 + 1) * HW + pos];
        kk.z = g_conv1[(128 + n * 4 + 2) * HW + pos];
        kk.w = g_conv1[(128 + n * 4 + 3) * HW + pos];
        vv.x = g_conv1[(160 + n * 4 + 0) * HW + pos];
        vv.y = g_conv1[(160 + n * 4 + 1) * HW + pos];
        vv.z = g_conv1[(160 + n * 4 + 2) * HW + pos];
        vv.w = g_conv1[(160 + n * 4 + 3) * HW + pos];
        s_k[t] = l2n(kk);
        s_v[t] = vv;
    }
    __syncthreads();
    if (t >= 240) return;

    const int pos = h * IMGW + t;
    float4 q;
    q.x = g_conv1[(256 + n * 4 + 0) * HW + pos];
    q.y = g_conv1[(256 + n * 4 + 1) * HW + pos];
    q.z = g_conv1[(256 + n * 4 + 2) * HW + pos];
    q.w = g_conv1[(256 + n * 4 + 3) * HW + pos];
    q = l2n(q);
    const float sc = s_sc;

    float m = -1e30f, l = 0.f;
    float ax = 0, ay = 0, az = 0, aw = 0;
    for (int j = 0; j < 240; j++) {
        float4 kj = s_k[j];
        float s = sc * (q.x * kj.x + q.y * kj.y + q.z * kj.z + q.w * kj.w);
        float mn = fmaxf(m, s);
        float corr = __expf(m - mn);
        float w = __expf(s - mn);
        float4 vj = s_v[j];
        l = l * corr + w;
        ax = ax * corr + w * vj.x;
        ay = ay * corr + w * vj.y;
        az = az * corr + w * vj.z;
        aw = aw * corr + w * vj.w;
        m = mn;
    }
    float invl = 1.f / l;
    g_v1[(n * 4 + 0) * HW + pos] = ax * invl;
    g_v1[(n * 4 + 1) * HW + pos] = ay * invl;
    g_v1[(n * 4 + 2) * HW + pos] = az * invl;
    g_v1[(n * 4 + 3) * HW + pos] = aw * invl;
}

// ---------------------------------------------------------------------------
// Branch 2, pass 2: column attention.
// ---------------------------------------------------------------------------
__global__ __launch_bounds__(256) void axial_col_kernel(const float* __restrict__ lrls) {
    const int n = blockIdx.x / IMGW, w = blockIdx.x % IMGW;
    const int t = threadIdx.x;
    __shared__ float4 s_k[240], s_v[240];
    __shared__ float s_sc;
    if (t == 0) s_sc = expf(fminf(lrls[n], LOG_MAX));

    if (t < 240) {
        const int pos = t * IMGW + w;
        float4 kk, vv;
        kk.x = g_conv1[(128 + n * 4 + 0) * HW + pos];
        kk.y = g_conv1[(128 + n * 4 + 1) * HW + pos];
        kk.z = g_conv1[(128 + n * 4 + 2) * HW + pos];
        kk.w = g_conv1[(128 + n * 4 + 3) * HW + pos];
        vv.x = g_v1[(n * 4 + 0) * HW + pos];
        vv.y = g_v1[(n * 4 + 1) * HW + pos];
        vv.z = g_v1[(n * 4 + 2) * HW + pos];
        vv.w = g_v1[(n * 4 + 3) * HW + pos];
        s_k[t] = l2n(kk);
        s_v[t] = vv;
    }
    __syncthreads();
    if (t >= 240) return;

    const int pos = t * IMGW + w;
    float4 q;
    q.x = g_conv1[(256 + n * 4 + 0) * HW + pos];
    q.y = g_conv1[(256 + n * 4 + 1) * HW + pos];
    q.z = g_conv1[(256 + n * 4 + 2) * HW + pos];
    q.w = g_conv1[(256 + n * 4 + 3) * HW + pos];
    q = l2n(q);
    const float sc = s_sc;

    float m = -1e30f, l = 0.f;
    float ax = 0, ay = 0, az = 0, aw = 0;
    for (int j = 0; j < 240; j++) {
        float4 kj = s_k[j];
        float s = sc * (q.x * kj.x + q.y * kj.y + q.z * kj.z + q.w * kj.w);
        float mn = fmaxf(m, s);
        float corr = __expf(m - mn);
        float wgt = __expf(s - mn);
        float4 vj = s_v[j];
        l = l * corr + wgt;
        ax = ax * corr + wgt * vj.x;
        ay = ay * corr + wgt * vj.y;
        az = az * corr + wgt * vj.z;
        aw = aw * corr + wgt * vj.w;
        m = mn;
    }
    float invl = 1.f / l;
    g_y[(64 + n * 4 + 0) * HW + pos] = ax * invl;
    g_y[(64 + n * 4 + 1) * HW + pos] = ay * invl;
    g_y[(64 + n * 4 + 2) * HW + pos] = az * invl;
    g_y[(64 + n * 4 + 3) * HW + pos] = aw * invl;
}

// ---------------------------------------------------------------------------
extern "C" void kernel_launch(void* const* d_in, const int* in_sizes, int n_in,
                              void* d_out, int out_size) {
    const float* x      = (const float*)d_in[0];
    const float* w_in   = (const float*)d_in[1];
    const float* b_in   = (const float*)d_in[2];
    const float* w_f    = (const float*)d_in[3];
    const float* b_f    = (const float*)d_in[4];
    const float* w_out  = (const float*)d_in[5];
    const float* b_out  = (const float*)d_in[6];
    const float* ls     = (const float*)d_in[7];
    const float* lr_ls  = (const float*)d_in[8];
    float* out = (float*)d_out;

    float* p_conv1; float* p_y; float* p_wrep;
    cudaGetSymbolAddress((void**)&p_conv1, g_conv1);
    cudaGetSymbolAddress((void**)&p_y, g_y);
    cudaGetSymbolAddress((void**)&p_wrep, g_wrep);

    const int SMEM_BYTES = 18176 * 4;  // 72704
    static int attr_set = 0;
    if (!attr_set) {
        cudaFuncSetAttribute(conv3x3_mma_kernel,
                             cudaFuncAttributeMaxDynamicSharedMemorySize, SMEM_BYTES);
        attr_set = 1;
    }

    const int W_IN_SZ = 2 * 192 * 864, W_F_SZ = 2 * 96 * 864;
    repack_w_kernel<<<(192 * 864 + 255) / 256, 256>>>(w_in, p_wrep, 192);
    repack_w_kernel<<<(96 * 864 + 255) / 256, 256>>>(w_f, p_wrep + W_IN_SZ, 96);
    repack_w_kernel<<<(96 * 864 + 255) / 256, 256>>>(w_out, p_wrep + W_IN_SZ + W_F_SZ, 96);

    dim3 cgrid(15, 30, 2);
    conv3x3_mma_kernel<<<cgrid, 256, SMEM_BYTES>>>(x, p_wrep, b_in, p_conv1, 192);
    dim3 cgrid1(15, 30, 1);
    conv3x3_mma_kernel<<<cgrid1, 256, SMEM_BYTES>>>(x, p_wrep + W_IN_SZ, b_f,
                                                    p_conv1 + 192 * HW, 96);

    win_attn_kernel<<<dim3(2304, 2), 256>>>(ls);
    axial_row_kernel<<<8 * IMGW, 256>>>(lr_ls);
    axial_col_kernel<<<8 * IMGW, 256>>>(lr_ls);

    conv3x3_mma_kernel<<<cgrid1, 256, SMEM_BYTES>>>(p_y, p_wrep + W_IN_SZ + W_F_SZ,
                                                    b_out, out, 96);
}

// round 4
// speedup vs baseline: 3.1591x; 2.9856x over previous
#include <cuda_runtime.h>
#include <cuda_bf16.h>
#include <math.h>

#define HW    57600
#define IMGW  240
#define LOG_MAX 4.6051701859880914f  // log(1/0.01)

// Scratch (allocation-free):
__device__ float g_conv1[288 * HW];   // [0:192)=xp (conv_in), [192:288)=fp (conv_f)
__device__ float g_y[96 * HW];        // concat of 3 attention branch outputs
__device__ float g_v1[32 * HW];       // row-attention intermediate for branch 2
__device__ float g_wrep[768 * 864];   // repacked bf16x2 hi|lo weights (in|f|out)

__device__ __forceinline__ unsigned pack_bf2(float a, float b) {
    __nv_bfloat162 h;
    h.x = __float2bfloat16_rn(a);
    h.y = __float2bfloat16_rn(b);
    return *(unsigned*)&h;
}

// ---------------------------------------------------------------------------
// Repack OIHW weights -> [chunk(ic/16)][shift(9)][icpair(8)][oc] as bf16x2,
// hi array then lo (residual) array. Each word = (ic even, ic odd).
// ---------------------------------------------------------------------------
__global__ void repack_w_kernel(const float* __restrict__ wt,
                                unsigned* __restrict__ wrep, int Cout) {
    int idx = blockIdx.x * 256 + threadIdx.x;
    int total = Cout * 432;  // 6 * 9 * 8 * Cout
    if (idx >= total) return;
    int o = idx % Cout;
    int rem = idx / Cout;
    int p = rem % 8; rem /= 8;
    int s = rem % 9;
    int ch = rem / 9;
    int ic = ch * 16 + 2 * p;
    float v0 = wt[(o * 96 + ic) * 9 + s];
    float v1 = wt[(o * 96 + ic + 1) * 9 + s];
    __nv_bfloat16 h0 = __float2bfloat16_rn(v0);
    __nv_bfloat16 h1 = __float2bfloat16_rn(v1);
    float r0 = v0 - __bfloat162float(h0);
    float r1 = v1 - __bfloat162float(h1);
    __nv_bfloat162 hi; hi.x = h0; hi.y = h1;
    wrep[idx] = *(unsigned*)&hi;
    wrep[total + idx] = pack_bf2(r0, r1);
}

// ---------------------------------------------------------------------------
// Implicit-GEMM 3x3 conv via mma.sync.m16n8k16 bf16, 2-way split (3 products).
// Block tile: 8x16 pixels (M=128) x 96 oc (N=96); 8 warps (wm 0..1, wn 0..3).
// K loop: 6 chunks of 16 input channels x 9 shifts (K=16 per MMA).
// Dynamic smem (unsigned words):
//   [0,1600)      A hi  [icpair8][y10][x20]  (half2: ic even|odd)
//   [1600,3200)   A lo
//   [3200,10688)  B hi  [72 = s*8+icpair][104]
//   [10688,18176) B lo
// ---------------------------------------------------------------------------
__global__ __launch_bounds__(256, 2) void conv3x3_mma_kernel(
    const float* __restrict__ in, const unsigned* __restrict__ wrep,
    const float* __restrict__ bias, float* __restrict__ out, int Cout) {
    extern __shared__ unsigned smem[];
    unsigned* s_a_hi = smem;
    unsigned* s_a_lo = smem + 1600;
    unsigned* s_b_hi = smem + 3200;
    unsigned* s_b_lo = smem + 10688;

    const int tid = threadIdx.x;
    const int lane = tid & 31, w = tid >> 5;
    const int wm = w & 1, wn = w >> 1;
    const int x0 = blockIdx.x * 16, y0 = blockIdx.y * 8;
    const int oc_blk = blockIdx.z * 96;
    const int g = lane >> 2, t = lane & 3;  // groupID, threadID_in_group
    const int wlo = Cout * 432;             // lo-part offset in wrep

    float acc[4][3][4];
#pragma unroll
    for (int j = 0; j < 3; j++) {
        int oc = oc_blk + wn * 24 + j * 8 + 2 * t;
        float b0 = bias[oc], b1 = bias[oc + 1];
#pragma unroll
        for (int i = 0; i < 4; i++) {
            acc[i][j][0] = b0; acc[i][j][1] = b1;
            acc[i][j][2] = b0; acc[i][j][3] = b1;
        }
    }

    for (int ch = 0; ch < 6; ch++) {
        __syncthreads();
        // stage A halo: 8 ic-pairs x 10 x 18, zero-padded borders, hi+lo bf16x2
        for (int idx = tid; idx < 8 * 180; idx += 256) {
            int p = idx / 180, rem = idx % 180;
            int ly = rem / 18, lx = rem % 18;
            int gy = y0 - 1 + ly, gx = x0 - 1 + lx;
            float v0 = 0.f, v1 = 0.f;
            if (gy >= 0 && gy < IMGW && gx >= 0 && gx < IMGW) {
                const float* base = in + (ch * 16 + 2 * p) * HW + gy * IMGW + gx;
                v0 = base[0];
                v1 = base[HW];
            }
            __nv_bfloat16 h0 = __float2bfloat16_rn(v0);
            __nv_bfloat16 h1 = __float2bfloat16_rn(v1);
            float r0 = v0 - __bfloat162float(h0);
            float r1 = v1 - __bfloat162float(h1);
            int off = p * 200 + ly * 20 + lx;
            __nv_bfloat162 hh; hh.x = h0; hh.y = h1;
            s_a_hi[off] = *(unsigned*)&hh;
            s_a_lo[off] = pack_bf2(r0, r1);
        }
        // stage B: 72 rows x 96 oc words (bf16x2), hi+lo, vectorized
        for (int idx = tid; idx < 72 * 24; idx += 256) {
            int r = idx / 24, c = idx % 24;
            const unsigned* src = wrep + (ch * 72 + r) * Cout + oc_blk + c * 4;
            *(uint4*)&s_b_hi[r * 104 + c * 4] = *(const uint4*)src;
            *(uint4*)&s_b_lo[r * 104 + c * 4] = *(const uint4*)(src + wlo);
        }
        __syncthreads();

#pragma unroll 3
        for (int s = 0; s < 9; s++) {
            const int dy = s / 3, dx = s % 3;  // halo idx: py+dy, px+dx
            unsigned bh[3][2], bl[3][2];
#pragma unroll
            for (int j = 0; j < 3; j++) {
                int oc = wn * 24 + j * 8 + g;
                bh[j][0] = s_b_hi[(s * 8 + t) * 104 + oc];
                bh[j][1] = s_b_hi[(s * 8 + t + 4) * 104 + oc];
                bl[j][0] = s_b_lo[(s * 8 + t) * 104 + oc];
                bl[j][1] = s_b_lo[(s * 8 + t + 4) * 104 + oc];
            }
#pragma unroll
            for (int i = 0; i < 4; i++) {
                int py = wm * 4 + i;
                int o00 = t * 200 + (py + dy) * 20 + g + dx;
                int o4  = o00 + 800;  // icpair t+4
                unsigned ah0 = s_a_hi[o00], ah1 = s_a_hi[o00 + 8];
                unsigned ah2 = s_a_hi[o4],  ah3 = s_a_hi[o4 + 8];
                unsigned al0 = s_a_lo[o00], al1 = s_a_lo[o00 + 8];
                unsigned al2 = s_a_lo[o4],  al3 = s_a_lo[o4 + 8];
#pragma unroll
                for (int j = 0; j < 3; j++) {
                    asm volatile(
                        "mma.sync.aligned.m16n8k16.row.col.f32.bf16.bf16.f32 "
                        "{%0,%1,%2,%3}, {%4,%5,%6,%7}, {%8,%9}, {%0,%1,%2,%3};"
                        : "+f"(acc[i][j][0]), "+f"(acc[i][j][1]),
                          "+f"(acc[i][j][2]), "+f"(acc[i][j][3])
                        : "r"(al0), "r"(al1), "r"(al2), "r"(al3),
                          "r"(bh[j][0]), "r"(bh[j][1]));
                    asm volatile(
                        "mma.sync.aligned.m16n8k16.row.col.f32.bf16.bf16.f32 "
                        "{%0,%1,%2,%3}, {%4,%5,%6,%7}, {%8,%9}, {%0,%1,%2,%3};"
                        : "+f"(acc[i][j][0]), "+f"(acc[i][j][1]),
                          "+f"(acc[i][j][2]), "+f"(acc[i][j][3])
                        : "r"(ah0), "r"(ah1), "r"(ah2), "r"(ah3),
                          "r"(bl[j][0]), "r"(bl[j][1]));
                    asm volatile(
                        "mma.sync.aligned.m16n8k16.row.col.f32.bf16.bf16.f32 "
                        "{%0,%1,%2,%3}, {%4,%5,%6,%7}, {%8,%9}, {%0,%1,%2,%3};"
                        : "+f"(acc[i][j][0]), "+f"(acc[i][j][1]),
                          "+f"(acc[i][j][2]), "+f"(acc[i][j][3])
                        : "r"(ah0), "r"(ah1), "r"(ah2), "r"(ah3),
                          "r"(bh[j][0]), "r"(bh[j][1]));
                }
            }
        }
    }

    // epilogue: c0 (px=g, oc), c1 (px=g, oc+1), c2 (px=g+8, oc), c3 (px=g+8, oc+1)
    const int gx0 = x0 + g;
#pragma unroll
    for (int i = 0; i < 4; i++) {
        int gy = y0 + wm * 4 + i;
#pragma unroll
        for (int j = 0; j < 3; j++) {
            int oc = oc_blk + wn * 24 + j * 8 + 2 * t;
            out[oc * HW + gy * IMGW + gx0] = acc[i][j][0];
            out[(oc + 1) * HW + gy * IMGW + gx0] = acc[i][j][1];
            out[oc * HW + gy * IMGW + gx0 + 8] = acc[i][j][2];
            out[(oc + 1) * HW + gy * IMGW + gx0 + 8] = acc[i][j][3];
        }
    }
}

__device__ __forceinline__ float4 l2n(float4 a) {
    float n = sqrtf(a.x * a.x + a.y * a.y + a.z * a.z + a.w * a.w);
    float inv = 1.f / fmaxf(n, 1e-12f);
    a.x *= inv; a.y *= inv; a.z *= inv; a.w *= inv;
    return a;
}

// ---------------------------------------------------------------------------
// Window attention (branches 0 and 1). One block per (window, branch).
// ---------------------------------------------------------------------------
__global__ __launch_bounds__(256) void win_attn_kernel(const float* __restrict__ ls) {
    const int branch = blockIdx.y;
    const int win = blockIdx.x;
    const int Hw = win / 48, Ww = win % 48;
    const int t = threadIdx.x;

    __shared__ float4 s_k[8][25];
    __shared__ float4 s_v[8][25];
    __shared__ float s_sc[8];

    if (t < 8) s_sc[t] = expf(fminf(ls[t], LOG_MAX));

    const int n = t / 25, tok = t % 25;
    const int wy = tok / 5, wx = tok % 5;
    const int py = Hw * 5 + wy, px = Ww * 5 + wx;
    int gy = py, gx = px;
    if (branch) { gy = (gy + 3) % IMGW; gx = (gx + 3) % IMGW; }
    const int pos = gy * IMGW + gx;

    if (t < 200) {
        const float* xb = g_conv1 + branch * 64 * HW;
        float4 kk, vv;
        kk.x = xb[(n * 4 + 0) * HW + pos];
        kk.y = xb[(n * 4 + 1) * HW + pos];
        kk.z = xb[(n * 4 + 2) * HW + pos];
        kk.w = xb[(n * 4 + 3) * HW + pos];
        vv.x = xb[(32 + n * 4 + 0) * HW + pos];
        vv.y = xb[(32 + n * 4 + 1) * HW + pos];
        vv.z = xb[(32 + n * 4 + 2) * HW + pos];
        vv.w = xb[(32 + n * 4 + 3) * HW + pos];
        s_k[n][tok] = l2n(kk);
        s_v[n][tok] = vv;
    }
    __syncthreads();
    if (t >= 200) return;

    const float* fb = g_conv1 + (192 + branch * 32) * HW;
    float4 q;
    q.x = fb[(n * 4 + 0) * HW + pos];
    q.y = fb[(n * 4 + 1) * HW + pos];
    q.z = fb[(n * 4 + 2) * HW + pos];
    q.w = fb[(n * 4 + 3) * HW + pos];
    q = l2n(q);
    const float sc = s_sc[n];

    float m = -1e30f, l = 0.f;
    float ax = 0, ay = 0, az = 0, aw = 0;
#pragma unroll
    for (int j = 0; j < 25; j++) {
        float4 kj = s_k[n][j];
        float s = sc * (q.x * kj.x + q.y * kj.y + q.z * kj.z + q.w * kj.w);
        float mn = fmaxf(m, s);
        float corr = __expf(m - mn);
        float w = __expf(s - mn);
        float4 vj = s_v[n][j];
        l = l * corr + w;
        ax = ax * corr + w * vj.x;
        ay = ay * corr + w * vj.y;
        az = az * corr + w * vj.z;
        aw = aw * corr + w * vj.w;
        m = mn;
    }
    float invl = 1.f / l;

    int oy = py, ox = px;
    if (branch) { oy = (oy + 2) % IMGW; ox = (ox + 2) % IMGW; }
    const int opos = oy * IMGW + ox;
    float* yb = g_y + branch * 32 * HW;
    yb[(n * 4 + 0) * HW + opos] = ax * invl;
    yb[(n * 4 + 1) * HW + opos] = ay * invl;
    yb[(n * 4 + 2) * HW + opos] = az * invl;
    yb[(n * 4 + 3) * HW + opos] = aw * invl;
}

// ---------------------------------------------------------------------------
// Branch 2, pass 1: row attention.
// ---------------------------------------------------------------------------
__global__ __launch_bounds__(256) void axial_row_kernel(const float* __restrict__ lrls) {
    const int n = blockIdx.x / IMGW, h = blockIdx.x % IMGW;
    const int t = threadIdx.x;
    __shared__ float4 s_k[240], s_v[240];
    __shared__ float s_sc;
    if (t == 0) s_sc = expf(fminf(lrls[n], LOG_MAX));

    if (t < 240) {
        const int pos = h * IMGW + t;
        float4 kk, vv;
        kk.x = g_conv1[(128 + n * 4 + 0) * HW + pos];
        kk.y = g_conv1[(128 + n * 4 + 1) * HW + pos];
        kk.z = g_conv1[(128 + n * 4 + 2) * HW + pos];
        kk.w = g_conv1[(128 + n * 4 + 3) * HW + pos];
        vv.x = g_conv1[(160 + n * 4 + 0) * HW + pos];
        vv.y = g_conv1[(160 + n * 4 + 1) * HW + pos];
        vv.z = g_conv1[(160 + n * 4 + 2) * HW + pos];
        vv.w = g_conv1[(160 + n * 4 + 3) * HW + pos];
        s_k[t] = l2n(kk);
        s_v[t] = vv;
    }
    __syncthreads();
    if (t >= 240) return;

    const int pos = h * IMGW + t;
    float4 q;
    q.x = g_conv1[(256 + n * 4 + 0) * HW + pos];
    q.y = g_conv1[(256 + n * 4 + 1) * HW + pos];
    q.z = g_conv1[(256 + n * 4 + 2) * HW + pos];
    q.w = g_conv1[(256 + n * 4 + 3) * HW + pos];
    q = l2n(q);
    const float sc = s_sc;

    float m = -1e30f, l = 0.f;
    float ax = 0, ay = 0, az = 0, aw = 0;
    for (int j = 0; j < 240; j++) {
        float4 kj = s_k[j];
        float s = sc * (q.x * kj.x + q.y * kj.y + q.z * kj.z + q.w * kj.w);
        float mn = fmaxf(m, s);
        float corr = __expf(m - mn);
        float w = __expf(s - mn);
        float4 vj = s_v[j];
        l = l * corr + w;
        ax = ax * corr + w * vj.x;
        ay = ay * corr + w * vj.y;
        az = az * corr + w * vj.z;
        aw = aw * corr + w * vj.w;
        m = mn;
    }
    float invl = 1.f / l;
    g_v1[(n * 4 + 0) * HW + pos] = ax * invl;
    g_v1[(n * 4 + 1) * HW + pos] = ay * invl;
    g_v1[(n * 4 + 2) * HW + pos] = az * invl;
    g_v1[(n * 4 + 3) * HW + pos] = aw * invl;
}

// ---------------------------------------------------------------------------
// Branch 2, pass 2: column attention.
// ---------------------------------------------------------------------------
__global__ __launch_bounds__(256) void axial_col_kernel(const float* __restrict__ lrls) {
    const int n = blockIdx.x / IMGW, w = blockIdx.x % IMGW;
    const int t = threadIdx.x;
    __shared__ float4 s_k[240], s_v[240];
    __shared__ float s_sc;
    if (t == 0) s_sc = expf(fminf(lrls[n], LOG_MAX));

    if (t < 240) {
        const int pos = t * IMGW + w;
        float4 kk, vv;
        kk.x = g_conv1[(128 + n * 4 + 0) * HW + pos];
        kk.y = g_conv1[(128 + n * 4 + 1) * HW + pos];
        kk.z = g_conv1[(128 + n * 4 + 2) * HW + pos];
        kk.w = g_conv1[(128 + n * 4 + 3) * HW + pos];
        vv.x = g_v1[(n * 4 + 0) * HW + pos];
        vv.y = g_v1[(n * 4 + 1) * HW + pos];
        vv.z = g_v1[(n * 4 + 2) * HW + pos];
        vv.w = g_v1[(n * 4 + 3) * HW + pos];
        s_k[t] = l2n(kk);
        s_v[t] = vv;
    }
    __syncthreads();
    if (t >= 240) return;

    const int pos = t * IMGW + w;
    float4 q;
    q.x = g_conv1[(256 + n * 4 + 0) * HW + pos];
    q.y = g_conv1[(256 + n * 4 + 1) * HW + pos];
    q.z = g_conv1[(256 + n * 4 + 2) * HW + pos];
    q.w = g_conv1[(256 + n * 4 + 3) * HW + pos];
    q = l2n(q);
    const float sc = s_sc;

    float m = -1e30f, l = 0.f;
    float ax = 0, ay = 0, az = 0, aw = 0;
    for (int j = 0; j < 240; j++) {
        float4 kj = s_k[j];
        float s = sc * (q.x * kj.x + q.y * kj.y + q.z * kj.z + q.w * kj.w);
        float mn = fmaxf(m, s);
        float corr = __expf(m - mn);
        float wgt = __expf(s - mn);
        float4 vj = s_v[j];
        l = l * corr + wgt;
        ax = ax * corr + wgt * vj.x;
        ay = ay * corr + wgt * vj.y;
        az = az * corr + wgt * vj.z;
        aw = aw * corr + wgt * vj.w;
        m = mn;
    }
    float invl = 1.f / l;
    g_y[(64 + n * 4 + 0) * HW + pos] = ax * invl;
    g_y[(64 + n * 4 + 1) * HW + pos] = ay * invl;
    g_y[(64 + n * 4 + 2) * HW + pos] = az * invl;
    g_y[(64 + n * 4 + 3) * HW + pos] = aw * invl;
}

// ---------------------------------------------------------------------------
extern "C" void kernel_launch(void* const* d_in, const int* in_sizes, int n_in,
                              void* d_out, int out_size) {
    const float* x      = (const float*)d_in[0];
    const float* w_in   = (const float*)d_in[1];
    const float* b_in   = (const float*)d_in[2];
    const float* w_f    = (const float*)d_in[3];
    const float* b_f    = (const float*)d_in[4];
    const float* w_out  = (const float*)d_in[5];
    const float* b_out  = (const float*)d_in[6];
    const float* ls     = (const float*)d_in[7];
    const float* lr_ls  = (const float*)d_in[8];
    float* out = (float*)d_out;

    float* p_conv1; float* p_y; unsigned* p_wrep;
    cudaGetSymbolAddress((void**)&p_conv1, g_conv1);
    cudaGetSymbolAddress((void**)&p_y, g_y);
    cudaGetSymbolAddress((void**)&p_wrep, g_wrep);

    const int SMEM_BYTES = 18176 * 4;  // 72704
    static int attr_set = 0;
    if (!attr_set) {
        cudaFuncSetAttribute(conv3x3_mma_kernel,
                             cudaFuncAttributeMaxDynamicSharedMemorySize, SMEM_BYTES);
        attr_set = 1;
    }

    // hi+lo word counts per tensor
    const int W_IN_SZ = 2 * 192 * 432, W_F_SZ = 2 * 96 * 432;
    repack_w_kernel<<<(192 * 432 + 255) / 256, 256>>>(w_in, p_wrep, 192);
    repack_w_kernel<<<(96 * 432 + 255) / 256, 256>>>(w_f, p_wrep + W_IN_SZ, 96);
    repack_w_kernel<<<(96 * 432 + 255) / 256, 256>>>(w_out, p_wrep + W_IN_SZ + W_F_SZ, 96);

    dim3 cgrid(15, 30, 2);
    conv3x3_mma_kernel<<<cgrid, 256, SMEM_BYTES>>>(x, p_wrep, b_in, p_conv1, 192);
    dim3 cgrid1(15, 30, 1);
    conv3x3_mma_kernel<<<cgrid1, 256, SMEM_BYTES>>>(x, p_wrep + W_IN_SZ, b_f,
                                                    p_conv1 + 192 * HW, 96);

    win_attn_kernel<<<dim3(2304, 2), 256>>>(ls);
    axial_row_kernel<<<8 * IMGW, 256>>>(lr_ls);
    axial_col_kernel<<<8 * IMGW, 256>>>(lr_ls);

    conv3x3_mma_kernel<<<cgrid1, 256, SMEM_BYTES>>>(p_y, p_wrep + W_IN_SZ + W_F_SZ,
                                                    b_out, out, 96);
}

// round 5
// speedup vs baseline: 3.6355x; 1.1508x over previous
#include <cuda_runtime.h>
#include <cuda_bf16.h>
#include <math.h>

#define HW    57600
#define IMGW  240
#define LOG_MAX 4.6051701859880914f  // log(1/0.01)

// Scratch (allocation-free):
__device__ float g_conv1[288 * HW];   // [0:192)=xp (conv_in), [192:288)=fp (conv_f)
__device__ float g_y[96 * HW];        // concat of 3 attention branch outputs
__device__ float g_v1[32 * HW];       // row-attention intermediate for branch 2
__device__ unsigned g_wrep[768 * 864];// repacked bf16x2 hi|lo weights (in+f | out)
__device__ float g_bias[288];         // combined bias for fused conv

__device__ __forceinline__ unsigned pack_bf2(float a, float b) {
    __nv_bfloat162 h;
    h.x = __float2bfloat16_rn(a);
    h.y = __float2bfloat16_rn(b);
    return *(unsigned*)&h;
}

// ---------------------------------------------------------------------------
// Repack OIHW weights -> [chunk(ic/16)][shift(9)][icpair(8)][oc_global] bf16x2,
// hi array then lo (residual) array, within a region of CoutTotal channels.
// ---------------------------------------------------------------------------
__global__ void repack_w_kernel(const float* __restrict__ wt,
                                unsigned* __restrict__ wrep, int CoutLocal,
                                int ocOff, int CoutTotal) {
    int idx = blockIdx.x * 256 + threadIdx.x;
    int total = CoutLocal * 432;  // 6*9*8 * CoutLocal
    if (idx >= total) return;
    int o = idx % CoutLocal;
    int rem = idx / CoutLocal;    // (ch*9+s)*8+p
    int p = rem % 8; int rem2 = rem / 8;
    int s = rem2 % 9;
    int ch = rem2 / 9;
    int ic = ch * 16 + 2 * p;
    float v0 = wt[(o * 96 + ic) * 9 + s];
    float v1 = wt[(o * 96 + ic + 1) * 9 + s];
    __nv_bfloat16 h0 = __float2bfloat16_rn(v0);
    __nv_bfloat16 h1 = __float2bfloat16_rn(v1);
    float r0 = v0 - __bfloat162float(h0);
    float r1 = v1 - __bfloat162float(h1);
    __nv_bfloat162 hi; hi.x = h0; hi.y = h1;
    int dst = rem * CoutTotal + ocOff + o;
    wrep[dst] = *(unsigned*)&hi;
    wrep[CoutTotal * 432 + dst] = pack_bf2(r0, r1);
}

__global__ void bias_combine_kernel(const float* __restrict__ b_in,
                                    const float* __restrict__ b_f) {
    int i = threadIdx.x + blockIdx.x * 288;
    if (blockIdx.x == 0 && threadIdx.x < 288)
        g_bias[threadIdx.x] = threadIdx.x < 192 ? b_in[threadIdx.x]
                                                : b_f[threadIdx.x - 192];
    (void)i;
}

// ---------------------------------------------------------------------------
// Implicit-GEMM 3x3 conv via mma.sync.m16n8k16 bf16, 2-way split (3 products).
// Block tile: 8x16 pixels (M=128) x 96 oc; 8 warps (wm 0..1, wn 0..3).
// ---------------------------------------------------------------------------
__global__ __launch_bounds__(256, 2) void conv3x3_mma_kernel(
    const float* __restrict__ in, const unsigned* __restrict__ wrep,
    const float* __restrict__ bias, float* __restrict__ out, int Cout) {
    extern __shared__ unsigned smem[];
    unsigned* s_a_hi = smem;
    unsigned* s_a_lo = smem + 1600;
    unsigned* s_b_hi = smem + 3200;
    unsigned* s_b_lo = smem + 10688;

    const int tid = threadIdx.x;
    const int lane = tid & 31, w = tid >> 5;
    const int wm = w & 1, wn = w >> 1;
    const int x0 = blockIdx.x * 16, y0 = blockIdx.y * 8;
    const int oc_blk = blockIdx.z * 96;
    const int g = lane >> 2, t = lane & 3;
    const int wlo = Cout * 432;

    float acc[4][3][4];
#pragma unroll
    for (int j = 0; j < 3; j++) {
        int oc = oc_blk + wn * 24 + j * 8 + 2 * t;
        float b0 = bias[oc], b1 = bias[oc + 1];
#pragma unroll
        for (int i = 0; i < 4; i++) {
            acc[i][j][0] = b0; acc[i][j][1] = b1;
            acc[i][j][2] = b0; acc[i][j][3] = b1;
        }
    }

    for (int ch = 0; ch < 6; ch++) {
        __syncthreads();
        for (int idx = tid; idx < 8 * 180; idx += 256) {
            int p = idx / 180, rem = idx % 180;
            int ly = rem / 18, lx = rem % 18;
            int gy = y0 - 1 + ly, gx = x0 - 1 + lx;
            float v0 = 0.f, v1 = 0.f;
            if (gy >= 0 && gy < IMGW && gx >= 0 && gx < IMGW) {
                const float* base = in + (ch * 16 + 2 * p) * HW + gy * IMGW + gx;
                v0 = base[0];
                v1 = base[HW];
            }
            __nv_bfloat16 h0 = __float2bfloat16_rn(v0);
            __nv_bfloat16 h1 = __float2bfloat16_rn(v1);
            float r0 = v0 - __bfloat162float(h0);
            float r1 = v1 - __bfloat162float(h1);
            int off = p * 200 + ly * 20 + lx;
            __nv_bfloat162 hh; hh.x = h0; hh.y = h1;
            s_a_hi[off] = *(unsigned*)&hh;
            s_a_lo[off] = pack_bf2(r0, r1);
        }
        for (int idx = tid; idx < 72 * 24; idx += 256) {
            int r = idx / 24, c = idx % 24;
            const unsigned* src = wrep + (ch * 72 + r) * Cout + oc_blk + c * 4;
            *(uint4*)&s_b_hi[r * 104 + c * 4] = *(const uint4*)src;
            *(uint4*)&s_b_lo[r * 104 + c * 4] = *(const uint4*)(src + wlo);
        }
        __syncthreads();

#pragma unroll 3
        for (int s = 0; s < 9; s++) {
            const int dy = s / 3, dx = s % 3;
            unsigned bh[3][2], bl[3][2];
#pragma unroll
            for (int j = 0; j < 3; j++) {
                int oc = wn * 24 + j * 8 + g;
                bh[j][0] = s_b_hi[(s * 8 + t) * 104 + oc];
                bh[j][1] = s_b_hi[(s * 8 + t + 4) * 104 + oc];
                bl[j][0] = s_b_lo[(s * 8 + t) * 104 + oc];
                bl[j][1] = s_b_lo[(s * 8 + t + 4) * 104 + oc];
            }
#pragma unroll
            for (int i = 0; i < 4; i++) {
                int py = wm * 4 + i;
                int o00 = t * 200 + (py + dy) * 20 + g + dx;
                int o4  = o00 + 800;
                unsigned ah0 = s_a_hi[o00], ah1 = s_a_hi[o00 + 8];
                unsigned ah2 = s_a_hi[o4],  ah3 = s_a_hi[o4 + 8];
                unsigned al0 = s_a_lo[o00], al1 = s_a_lo[o00 + 8];
                unsigned al2 = s_a_lo[o4],  al3 = s_a_lo[o4 + 8];
#pragma unroll
                for (int j = 0; j < 3; j++) {
                    asm volatile(
                        "mma.sync.aligned.m16n8k16.row.col.f32.bf16.bf16.f32 "
                        "{%0,%1,%2,%3}, {%4,%5,%6,%7}, {%8,%9}, {%0,%1,%2,%3};"
                        : "+f"(acc[i][j][0]), "+f"(acc[i][j][1]),
                          "+f"(acc[i][j][2]), "+f"(acc[i][j][3])
                        : "r"(al0), "r"(al1), "r"(al2), "r"(al3),
                          "r"(bh[j][0]), "r"(bh[j][1]));
                    asm volatile(
                        "mma.sync.aligned.m16n8k16.row.col.f32.bf16.bf16.f32 "
                        "{%0,%1,%2,%3}, {%4,%5,%6,%7}, {%8,%9}, {%0,%1,%2,%3};"
                        : "+f"(acc[i][j][0]), "+f"(acc[i][j][1]),
                          "+f"(acc[i][j][2]), "+f"(acc[i][j][3])
                        : "r"(ah0), "r"(ah1), "r"(ah2), "r"(ah3),
                          "r"(bl[j][0]), "r"(bl[j][1]));
                    asm volatile(
                        "mma.sync.aligned.m16n8k16.row.col.f32.bf16.bf16.f32 "
                        "{%0,%1,%2,%3}, {%4,%5,%6,%7}, {%8,%9}, {%0,%1,%2,%3};"
                        : "+f"(acc[i][j][0]), "+f"(acc[i][j][1]),
                          "+f"(acc[i][j][2]), "+f"(acc[i][j][3])
                        : "r"(ah0), "r"(ah1), "r"(ah2), "r"(ah3),
                          "r"(bh[j][0]), "r"(bh[j][1]));
                }
            }
        }
    }

    const int gx0 = x0 + g;
#pragma unroll
    for (int i = 0; i < 4; i++) {
        int gy = y0 + wm * 4 + i;
#pragma unroll
        for (int j = 0; j < 3; j++) {
            int oc = oc_blk + wn * 24 + j * 8 + 2 * t;
            out[oc * HW + gy * IMGW + gx0] = acc[i][j][0];
            out[(oc + 1) * HW + gy * IMGW + gx0] = acc[i][j][1];
            out[oc * HW + gy * IMGW + gx0 + 8] = acc[i][j][2];
            out[(oc + 1) * HW + gy * IMGW + gx0 + 8] = acc[i][j][3];
        }
    }
}

__device__ __forceinline__ float4 l2n(float4 a) {
    float n = sqrtf(a.x * a.x + a.y * a.y + a.z * a.z + a.w * a.w);
    float inv = 1.f / fmaxf(n, 1e-12f);
    a.x *= inv; a.y *= inv; a.z *= inv; a.w *= inv;
    return a;
}

// ---------------------------------------------------------------------------
// Window attention (branches 0,1). Fixed-max softmax: scores = sc*cos <= sc,
// so shift by sc (valid upper bound) -> no online max, no rescale chain.
// ---------------------------------------------------------------------------
__global__ __launch_bounds__(256) void win_attn_kernel(const float* __restrict__ ls) {
    const int branch = blockIdx.y;
    const int win = blockIdx.x;
    const int Hw = win / 48, Ww = win % 48;
    const int t = threadIdx.x;

    __shared__ float4 s_k[8][25];
    __shared__ float4 s_v[8][25];
    __shared__ float s_sc[8];

    if (t < 8) s_sc[t] = expf(fminf(ls[t], LOG_MAX));

    const int n = t / 25, tok = t % 25;
    const int wy = tok / 5, wx = tok % 5;
    const int py = Hw * 5 + wy, px = Ww * 5 + wx;
    int gy = py, gx = px;
    if (branch) { gy = (gy + 3) % IMGW; gx = (gx + 3) % IMGW; }
    const int pos = gy * IMGW + gx;

    if (t < 200) {
        const float* xb = g_conv1 + branch * 64 * HW;
        float4 kk, vv;
        kk.x = xb[(n * 4 + 0) * HW + pos];
        kk.y = xb[(n * 4 + 1) * HW + pos];
        kk.z = xb[(n * 4 + 2) * HW + pos];
        kk.w = xb[(n * 4 + 3) * HW + pos];
        vv.x = xb[(32 + n * 4 + 0) * HW + pos];
        vv.y = xb[(32 + n * 4 + 1) * HW + pos];
        vv.z = xb[(32 + n * 4 + 2) * HW + pos];
        vv.w = xb[(32 + n * 4 + 3) * HW + pos];
        s_k[n][tok] = l2n(kk);
        s_v[n][tok] = vv;
    }
    __syncthreads();
    if (t >= 200) return;

    const float* fb = g_conv1 + (192 + branch * 32) * HW;
    float4 q;
    q.x = fb[(n * 4 + 0) * HW + pos];
    q.y = fb[(n * 4 + 1) * HW + pos];
    q.z = fb[(n * 4 + 2) * HW + pos];
    q.w = fb[(n * 4 + 3) * HW + pos];
    q = l2n(q);
    const float sc = s_sc[n];

    float l = 0.f, ax = 0, ay = 0, az = 0, aw = 0;
#pragma unroll
    for (int j = 0; j < 25; j++) {
        float4 kj = s_k[n][j];
        float s = sc * (q.x * kj.x + q.y * kj.y + q.z * kj.z + q.w * kj.w);
        float w = __expf(s - sc);
        float4 vj = s_v[n][j];
        l += w;
        ax += w * vj.x; ay += w * vj.y; az += w * vj.z; aw += w * vj.w;
    }
    float invl = 1.f / l;

    int oy = py, ox = px;
    if (branch) { oy = (oy + 2) % IMGW; ox = (ox + 2) % IMGW; }
    const int opos = oy * IMGW + ox;
    float* yb = g_y + branch * 32 * HW;
    yb[(n * 4 + 0) * HW + opos] = ax * invl;
    yb[(n * 4 + 1) * HW + opos] = ay * invl;
    yb[(n * 4 + 2) * HW + opos] = az * invl;
    yb[(n * 4 + 3) * HW + opos] = aw * invl;
}

// ---------------------------------------------------------------------------
// Branch 2, pass 1: row attention (fixed-max softmax).
// ---------------------------------------------------------------------------
__global__ __launch_bounds__(256) void axial_row_kernel(const float* __restrict__ lrls) {
    const int n = blockIdx.x / IMGW, h = blockIdx.x % IMGW;
    const int t = threadIdx.x;
    __shared__ float4 s_k[240], s_v[240];
    __shared__ float s_sc;
    if (t == 0) s_sc = expf(fminf(lrls[n], LOG_MAX));

    if (t < 240) {
        const int pos = h * IMGW + t;
        float4 kk, vv;
        kk.x = g_conv1[(128 + n * 4 + 0) * HW + pos];
        kk.y = g_conv1[(128 + n * 4 + 1) * HW + pos];
        kk.z = g_conv1[(128 + n * 4 + 2) * HW + pos];
        kk.w = g_conv1[(128 + n * 4 + 3) * HW + pos];
        vv.x = g_conv1[(160 + n * 4 + 0) * HW + pos];
        vv.y = g_conv1[(160 + n * 4 + 1) * HW + pos];
        vv.z = g_conv1[(160 + n * 4 + 2) * HW + pos];
        vv.w = g_conv1[(160 + n * 4 + 3) * HW + pos];
        s_k[t] = l2n(kk);
        s_v[t] = vv;
    }
    __syncthreads();
    if (t >= 240) return;

    const int pos = h * IMGW + t;
    float4 q;
    q.x = g_conv1[(256 + n * 4 + 0) * HW + pos];
    q.y = g_conv1[(256 + n * 4 + 1) * HW + pos];
    q.z = g_conv1[(256 + n * 4 + 2) * HW + pos];
    q.w = g_conv1[(256 + n * 4 + 3) * HW + pos];
    q = l2n(q);
    const float sc = s_sc;

    float l = 0.f, ax = 0, ay = 0, az = 0, aw = 0;
#pragma unroll 4
    for (int j = 0; j < 240; j++) {
        float4 kj = s_k[j];
        float s = sc * (q.x * kj.x + q.y * kj.y + q.z * kj.z + q.w * kj.w);
        float w = __expf(s - sc);
        float4 vj = s_v[j];
        l += w;
        ax += w * vj.x; ay += w * vj.y; az += w * vj.z; aw += w * vj.w;
    }
    float invl = 1.f / l;
    g_v1[(n * 4 + 0) * HW + pos] = ax * invl;
    g_v1[(n * 4 + 1) * HW + pos] = ay * invl;
    g_v1[(n * 4 + 2) * HW + pos] = az * invl;
    g_v1[(n * 4 + 3) * HW + pos] = aw * invl;
}

// ---------------------------------------------------------------------------
// Branch 2, pass 2: column attention (fixed-max softmax).
// ---------------------------------------------------------------------------
__global__ __launch_bounds__(256) void axial_col_kernel(const float* __restrict__ lrls) {
    const int n = blockIdx.x / IMGW, w = blockIdx.x % IMGW;
    const int t = threadIdx.x;
    __shared__ float4 s_k[240], s_v[240];
    __shared__ float s_sc;
    if (t == 0) s_sc = expf(fminf(lrls[n], LOG_MAX));

    if (t < 240) {
        const int pos = t * IMGW + w;
        float4 kk, vv;
        kk.x = g_conv1[(128 + n * 4 + 0) * HW + pos];
        kk.y = g_conv1[(128 + n * 4 + 1) * HW + pos];
        kk.z = g_conv1[(128 + n * 4 + 2) * HW + pos];
        kk.w = g_conv1[(128 + n * 4 + 3) * HW + pos];
        vv.x = g_v1[(n * 4 + 0) * HW + pos];
        vv.y = g_v1[(n * 4 + 1) * HW + pos];
        vv.z = g_v1[(n * 4 + 2) * HW + pos];
        vv.w = g_v1[(n * 4 + 3) * HW + pos];
        s_k[t] = l2n(kk);
        s_v[t] = vv;
    }
    __syncthreads();
    if (t >= 240) return;

    const int pos = t * IMGW + w;
    float4 q;
    q.x = g_conv1[(256 + n * 4 + 0) * HW + pos];
    q.y = g_conv1[(256 + n * 4 + 1) * HW + pos];
    q.z = g_conv1[(256 + n * 4 + 2) * HW + pos];
    q.w = g_conv1[(256 + n * 4 + 3) * HW + pos];
    q = l2n(q);
    const float sc = s_sc;

    float l = 0.f, ax = 0, ay = 0, az = 0, aw = 0;
#pragma unroll 4
    for (int j = 0; j < 240; j++) {
        float4 kj = s_k[j];
        float s = sc * (q.x * kj.x + q.y * kj.y + q.z * kj.z + q.w * kj.w);
        float wgt = __expf(s - sc);
        float4 vj = s_v[j];
        l += wgt;
        ax += wgt * vj.x; ay += wgt * vj.y; az += wgt * vj.z; aw += wgt * vj.w;
    }
    float invl = 1.f / l;
    g_y[(64 + n * 4 + 0) * HW + pos] = ax * invl;
    g_y[(64 + n * 4 + 1) * HW + pos] = ay * invl;
    g_y[(64 + n * 4 + 2) * HW + pos] = az * invl;
    g_y[(64 + n * 4 + 3) * HW + pos] = aw * invl;
}

// ---------------------------------------------------------------------------
extern "C" void kernel_launch(void* const* d_in, const int* in_sizes, int n_in,
                              void* d_out, int out_size) {
    const float* x      = (const float*)d_in[0];
    const float* w_in   = (const float*)d_in[1];
    const float* b_in   = (const float*)d_in[2];
    const float* w_f    = (const float*)d_in[3];
    const float* b_f    = (const float*)d_in[4];
    const float* w_out  = (const float*)d_in[5];
    const float* b_out  = (const float*)d_in[6];
    const float* ls     = (const float*)d_in[7];
    const float* lr_ls  = (const float*)d_in[8];
    float* out = (float*)d_out;

    float* p_conv1; float* p_y; unsigned* p_wrep; float* p_bias;
    cudaGetSymbolAddress((void**)&p_conv1, g_conv1);
    cudaGetSymbolAddress((void**)&p_y, g_y);
    cudaGetSymbolAddress((void**)&p_wrep, g_wrep);
    cudaGetSymbolAddress((void**)&p_bias, g_bias);

    const int SMEM_BYTES = 18176 * 4;  // 72704
    static int attr_set = 0;
    if (!attr_set) {
        cudaFuncSetAttribute(conv3x3_mma_kernel,
                             cudaFuncAttributeMaxDynamicSharedMemorySize, SMEM_BYTES);
        attr_set = 1;
    }

    // region 0: fused conv_in|conv_f, CoutTotal=288 (hi+lo = 2*288*432 words)
    // region 1: conv_out, CoutTotal=96
    unsigned* wrep_out = p_wrep + 2 * 288 * 432;
    repack_w_kernel<<<(192 * 432 + 255) / 256, 256>>>(w_in, p_wrep, 192, 0, 288);
    repack_w_kernel<<<(96 * 432 + 255) / 256, 256>>>(w_f, p_wrep, 96, 192, 288);
    repack_w_kernel<<<(96 * 432 + 255) / 256, 256>>>(w_out, wrep_out, 96, 0, 96);
    bias_combine_kernel<<<1, 288>>>(b_in, b_f);

    // fused conv_in + conv_f: 288 oc -> g_conv1 channels [0,288)
    conv3x3_mma_kernel<<<dim3(15, 30, 3), 256, SMEM_BYTES>>>(x, p_wrep, p_bias,
                                                             p_conv1, 288);

    win_attn_kernel<<<dim3(2304, 2), 256>>>(ls);
    axial_row_kernel<<<8 * IMGW, 256>>>(lr_ls);
    axial_col_kernel<<<8 * IMGW, 256>>>(lr_ls);

    conv3x3_mma_kernel<<<dim3(15, 30, 1), 256, SMEM_BYTES>>>(p_y, wrep_out,
                                                             b_out, out, 96);
}

// round 6
// speedup vs baseline: 4.1735x; 1.1480x over previous
#include <cuda_runtime.h>
#include <cuda_bf16.h>
#include <math.h>

#define HW    57600
#define IMGW  240
#define PW    244            // padded width (1 left + 3 right for alignment)
#define PH    242            // padded height
#define PHW   (PH * PW)      // 59048
#define LOG_MAX 4.6051701859880914f

// Scratch (allocation-free):
__device__ float    g_conv1[288 * HW];     // fp32 conv_in|conv_f outputs
__device__ float    g_v1[32 * HW];         // row-attention intermediate
__device__ unsigned g_wrep[768 * 864];     // repacked bf16x2 hi|lo weights
__device__ float    g_bias[288];
__device__ unsigned g_xa_hi[48 * PHW];     // padded bf16x2 input x (hi)
__device__ unsigned g_xa_lo[48 * PHW];
__device__ unsigned g_ya_hi[48 * PHW];     // padded bf16x2 attention output y
__device__ unsigned g_ya_lo[48 * PHW];

__device__ __forceinline__ unsigned pack_bf2(float a, float b) {
    __nv_bfloat162 h;
    h.x = __float2bfloat16_rn(a);
    h.y = __float2bfloat16_rn(b);
    return *(unsigned*)&h;
}

__device__ __forceinline__ unsigned smem_u32(const void* p) {
    return (unsigned)__cvta_generic_to_shared(p);
}
#define CP16(dst, src) asm volatile("cp.async.cg.shared.global [%0], [%1], 16;" :: "r"(dst), "l"(src))
#define CP8(dst, src)  asm volatile("cp.async.ca.shared.global [%0], [%1], 8;"  :: "r"(dst), "l"(src))
#define CP_COMMIT()    asm volatile("cp.async.commit_group;" ::: "memory")
#define CP_WAIT_ALL()  asm volatile("cp.async.wait_group 0;" ::: "memory")

// ---------------------------------------------------------------------------
// Precompute padded bf16x2 hi/lo input images from x (NCHW fp32, 96 ch).
// ---------------------------------------------------------------------------
__global__ void prep_x_kernel(const float* __restrict__ x) {
    int idx = blockIdx.x * 256 + threadIdx.x;
    if (idx >= 48 * PHW) return;
    int p = idx / PHW, rem = idx % PHW;
    int py = rem / PW, px = rem % PW;
    float v0 = 0.f, v1 = 0.f;
    if (py >= 1 && py <= 240 && px >= 1 && px <= 240) {
        int pos = (py - 1) * IMGW + (px - 1);
        v0 = x[(2 * p) * HW + pos];
        v1 = x[(2 * p + 1) * HW + pos];
    }
    __nv_bfloat16 h0 = __float2bfloat16_rn(v0);
    __nv_bfloat16 h1 = __float2bfloat16_rn(v1);
    __nv_bfloat162 hh; hh.x = h0; hh.y = h1;
    g_xa_hi[idx] = *(unsigned*)&hh;
    g_xa_lo[idx] = pack_bf2(v0 - __bfloat162float(h0), v1 - __bfloat162float(h1));
}

// Zero the borders of g_ya (interior written by attention kernels each launch).
__global__ void zero_yborder_kernel() {
    int idx = blockIdx.x * 256 + threadIdx.x;
    const int PER = 2 * PW + 4 * 240;  // 1448
    if (idx >= 48 * PER) return;
    int p = idx / PER, j = idx % PER;
    int py, px;
    if (j < 2 * PW) { py = (j / PW) ? 241 : 0; px = j % PW; }
    else {
        int k = j - 2 * PW;
        py = 1 + (k % 240);
        int c = k / 240;
        px = (c == 0) ? 0 : 240 + c;  // 0, 241, 242, 243
    }
    int o = p * PHW + py * PW + px;
    g_ya_hi[o] = 0u;
    g_ya_lo[o] = 0u;
}

// ---------------------------------------------------------------------------
// Repack OIHW weights -> [chunk(ic/16)][shift(9)][icpair(8)][oc_global] bf16x2
// hi then lo arrays within a region of CoutTotal channels.
// ---------------------------------------------------------------------------
__global__ void repack_w_kernel(const float* __restrict__ wt,
                                unsigned* __restrict__ wrep, int CoutLocal,
                                int ocOff, int CoutTotal) {
    int idx = blockIdx.x * 256 + threadIdx.x;
    int total = CoutLocal * 432;
    if (idx >= total) return;
    int o = idx % CoutLocal;
    int rem = idx / CoutLocal;
    int p = rem % 8; int rem2 = rem / 8;
    int s = rem2 % 9;
    int ch = rem2 / 9;
    int ic = ch * 16 + 2 * p;
    float v0 = wt[(o * 96 + ic) * 9 + s];
    float v1 = wt[(o * 96 + ic + 1) * 9 + s];
    __nv_bfloat16 h0 = __float2bfloat16_rn(v0);
    __nv_bfloat16 h1 = __float2bfloat16_rn(v1);
    __nv_bfloat162 hi; hi.x = h0; hi.y = h1;
    int dst = rem * CoutTotal + ocOff + o;
    wrep[dst] = *(unsigned*)&hi;
    wrep[CoutTotal * 432 + dst] =
        pack_bf2(v0 - __bfloat162float(h0), v1 - __bfloat162float(h1));
}

__global__ void bias_combine_kernel(const float* __restrict__ b_in,
                                    const float* __restrict__ b_f) {
    if (threadIdx.x < 288)
        g_bias[threadIdx.x] = threadIdx.x < 192 ? b_in[threadIdx.x]
                                                : b_f[threadIdx.x - 192];
}

// ---------------------------------------------------------------------------
// Implicit-GEMM 3x3 conv, m16n8k16 bf16, 2-way split. cp.async pipelined:
// A double-buffered (prefetch chunk+1), B single-buffered (XOR-8 swizzle).
// SMEM words: [0,3200) A buf0 (hi|lo), [3200,6400) A buf1,
//             [6400,13312) B hi [72][96], [13312,20224) B lo.
// ---------------------------------------------------------------------------
__global__ __launch_bounds__(256, 2) void conv3x3_mma_kernel(
    const unsigned* __restrict__ in_hi, const unsigned* __restrict__ in_lo,
    const unsigned* __restrict__ wrep, const float* __restrict__ bias,
    float* __restrict__ out, int Cout) {
    extern __shared__ unsigned smem[];
    unsigned* s_b_hi = smem + 6400;
    unsigned* s_b_lo = smem + 13312;

    const int tid = threadIdx.x;
    const int lane = tid & 31, w = tid >> 5;
    const int wm = w & 1, wn = w >> 1;
    const int x0 = blockIdx.x * 16, y0 = blockIdx.y * 8;
    const int oc_blk = blockIdx.z * 96;
    const int g = lane >> 2, t = lane & 3;
    const int wlo = Cout * 432;

    // -- staging lambdas --
    auto stage_a = [&](int ch, int buf) {
        unsigned* a_base = smem + buf * 3200;
        for (int i = tid; i < 800; i += 256) {
            int p = i / 100, r = i % 100;
            int ly = r / 10, seg = r % 10;
            int is_lo = seg >= 5, s5 = seg - is_lo * 5;
            int lx = s5 * 4;  // 0,4,8,12,16
            const unsigned* src = (is_lo ? in_lo : in_hi) +
                                  (ch * 8 + p) * PHW + (y0 + ly) * PW + x0 + lx;
            unsigned dst = smem_u32(a_base + is_lo * 1600 + p * 200 + ly * 20 + lx);
            if (s5 < 4) CP16(dst, src);
            else        CP8(dst, src);
        }
    };
    auto stage_b = [&](int ch) {
        for (int i = tid; i < 3456; i += 256) {
            int is_lo = i >= 1728, k = i - is_lo * 1728;
            int r = k / 24, c = k % 24;
            const unsigned* src = wrep + is_lo * wlo +
                                  (ch * 72 + r) * Cout + oc_blk + c * 4;
            int col = (c * 4) ^ ((r & 3) * 8);
            unsigned dst = smem_u32((is_lo ? s_b_lo : s_b_hi) + r * 96 + col);
            CP16(dst, src);
        }
    };

    float acc[4][3][4];
#pragma unroll
    for (int j = 0; j < 3; j++) {
        int oc = oc_blk + wn * 24 + j * 8 + 2 * t;
        float b0 = bias[oc], b1 = bias[oc + 1];
#pragma unroll
        for (int i = 0; i < 4; i++) {
            acc[i][j][0] = b0; acc[i][j][1] = b1;
            acc[i][j][2] = b0; acc[i][j][3] = b1;
        }
    }

    stage_a(0, 0);
    stage_b(0);
    CP_COMMIT();
    CP_WAIT_ALL();
    __syncthreads();

    for (int ch = 0; ch < 6; ch++) {
        if (ch < 5) { stage_a(ch + 1, (ch + 1) & 1); CP_COMMIT(); }

        const unsigned* a_hi = smem + (ch & 1) * 3200;
        const unsigned* a_lo = a_hi + 1600;

#pragma unroll 3
        for (int s = 0; s < 9; s++) {
            const int dy = s / 3, dx = s % 3;
            unsigned bh[3][2], bl[3][2];
            const int swz = t * 8;
#pragma unroll
            for (int j = 0; j < 3; j++) {
                int oc = (wn * 24 + j * 8 + g) ^ swz;
                bh[j][0] = s_b_hi[(s * 8 + t) * 96 + oc];
                bh[j][1] = s_b_hi[(s * 8 + t + 4) * 96 + oc];
                bl[j][0] = s_b_lo[(s * 8 + t) * 96 + oc];
                bl[j][1] = s_b_lo[(s * 8 + t + 4) * 96 + oc];
            }
#pragma unroll
            for (int i = 0; i < 4; i++) {
                int py = wm * 4 + i;
                int o00 = t * 200 + (py + dy) * 20 + g + dx;
                int o4  = o00 + 800;
                unsigned ah0 = a_hi[o00], ah1 = a_hi[o00 + 8];
                unsigned ah2 = a_hi[o4],  ah3 = a_hi[o4 + 8];
                unsigned al0 = a_lo[o00], al1 = a_lo[o00 + 8];
                unsigned al2 = a_lo[o4],  al3 = a_lo[o4 + 8];
#pragma unroll
                for (int j = 0; j < 3; j++) {
                    asm volatile(
                        "mma.sync.aligned.m16n8k16.row.col.f32.bf16.bf16.f32 "
                        "{%0,%1,%2,%3}, {%4,%5,%6,%7}, {%8,%9}, {%0,%1,%2,%3};"
                        : "+f"(acc[i][j][0]), "+f"(acc[i][j][1]),
                          "+f"(acc[i][j][2]), "+f"(acc[i][j][3])
                        : "r"(al0), "r"(al1), "r"(al2), "r"(al3),
                          "r"(bh[j][0]), "r"(bh[j][1]));
                    asm volatile(
                        "mma.sync.aligned.m16n8k16.row.col.f32.bf16.bf16.f32 "
                        "{%0,%1,%2,%3}, {%4,%5,%6,%7}, {%8,%9}, {%0,%1,%2,%3};"
                        : "+f"(acc[i][j][0]), "+f"(acc[i][j][1]),
                          "+f"(acc[i][j][2]), "+f"(acc[i][j][3])
                        : "r"(ah0), "r"(ah1), "r"(ah2), "r"(ah3),
                          "r"(bl[j][0]), "r"(bl[j][1]));
                    asm volatile(
                        "mma.sync.aligned.m16n8k16.row.col.f32.bf16.bf16.f32 "
                        "{%0,%1,%2,%3}, {%4,%5,%6,%7}, {%8,%9}, {%0,%1,%2,%3};"
                        : "+f"(acc[i][j][0]), "+f"(acc[i][j][1]),
                          "+f"(acc[i][j][2]), "+f"(acc[i][j][3])
                        : "r"(ah0), "r"(ah1), "r"(ah2), "r"(ah3),
                          "r"(bh[j][0]), "r"(bh[j][1]));
                }
            }
        }
        __syncthreads();  // all warps done reading B (and old A buf)
        if (ch < 5) {
            stage_b(ch + 1);
            CP_COMMIT();
            CP_WAIT_ALL();   // waits B(ch+1) and A(ch+1)
            __syncthreads();
        }
    }

    const int gx0 = x0 + g;
#pragma unroll
    for (int i = 0; i < 4; i++) {
        int gy = y0 + wm * 4 + i;
#pragma unroll
        for (int j = 0; j < 3; j++) {
            int oc = oc_blk + wn * 24 + j * 8 + 2 * t;
            out[oc * HW + gy * IMGW + gx0] = acc[i][j][0];
            out[(oc + 1) * HW + gy * IMGW + gx0] = acc[i][j][1];
            out[oc * HW + gy * IMGW + gx0 + 8] = acc[i][j][2];
            out[(oc + 1) * HW + gy * IMGW + gx0 + 8] = acc[i][j][3];
        }
    }
}

__device__ __forceinline__ float4 l2n(float4 a) {
    float n = sqrtf(a.x * a.x + a.y * a.y + a.z * a.z + a.w * a.w);
    float inv = 1.f / fmaxf(n, 1e-12f);
    a.x *= inv; a.y *= inv; a.z *= inv; a.w *= inv;
    return a;
}

// Store a channel-pair of y directly in padded bf16x2 hi/lo format.
__device__ __forceinline__ void store_y_pair(int pair, int ppos, float a, float b) {
    __nv_bfloat16 ha = __float2bfloat16_rn(a), hb = __float2bfloat16_rn(b);
    __nv_bfloat162 hh; hh.x = ha; hh.y = hb;
    g_ya_hi[pair * PHW + ppos] = *(unsigned*)&hh;
    g_ya_lo[pair * PHW + ppos] =
        pack_bf2(a - __bfloat162float(ha), b - __bfloat162float(hb));
}

// ---------------------------------------------------------------------------
// Window attention (branches 0,1), fixed-max softmax.
// ---------------------------------------------------------------------------
__global__ __launch_bounds__(256) void win_attn_kernel(const float* __restrict__ ls) {
    const int branch = blockIdx.y;
    const int win = blockIdx.x;
    const int Hw = win / 48, Ww = win % 48;
    const int t = threadIdx.x;

    __shared__ float4 s_k[8][25];
    __shared__ float4 s_v[8][25];
    __shared__ float s_sc[8];

    if (t < 8) s_sc[t] = expf(fminf(ls[t], LOG_MAX));

    const int n = t / 25, tok = t % 25;
    const int wy = tok / 5, wx = tok % 5;
    const int py = Hw * 5 + wy, px = Ww * 5 + wx;
    int gy = py, gx = px;
    if (branch) { gy = (gy + 3) % IMGW; gx = (gx + 3) % IMGW; }
    const int pos = gy * IMGW + gx;

    if (t < 200) {
        const float* xb = g_conv1 + branch * 64 * HW;
        float4 kk, vv;
        kk.x = xb[(n * 4 + 0) * HW + pos];
        kk.y = xb[(n * 4 + 1) * HW + pos];
        kk.z = xb[(n * 4 + 2) * HW + pos];
        kk.w = xb[(n * 4 + 3) * HW + pos];
        vv.x = xb[(32 + n * 4 + 0) * HW + pos];
        vv.y = xb[(32 + n * 4 + 1) * HW + pos];
        vv.z = xb[(32 + n * 4 + 2) * HW + pos];
        vv.w = xb[(32 + n * 4 + 3) * HW + pos];
        s_k[n][tok] = l2n(kk);
        s_v[n][tok] = vv;
    }
    __syncthreads();
    if (t >= 200) return;

    const float* fb = g_conv1 + (192 + branch * 32) * HW;
    float4 q;
    q.x = fb[(n * 4 + 0) * HW + pos];
    q.y = fb[(n * 4 + 1) * HW + pos];
    q.z = fb[(n * 4 + 2) * HW + pos];
    q.w = fb[(n * 4 + 3) * HW + pos];
    q = l2n(q);
    const float sc = s_sc[n];

    float l = 0.f, ax = 0, ay = 0, az = 0, aw = 0;
#pragma unroll
    for (int j = 0; j < 25; j++) {
        float4 kj = s_k[n][j];
        float s = sc * (q.x * kj.x + q.y * kj.y + q.z * kj.z + q.w * kj.w);
        float wgt = __expf(s - sc);
        float4 vj = s_v[n][j];
        l += wgt;
        ax += wgt * vj.x; ay += wgt * vj.y; az += wgt * vj.z; aw += wgt * vj.w;
    }
    float invl = 1.f / l;

    int oy = py, ox = px;
    if (branch) { oy = (oy + 2) % IMGW; ox = (ox + 2) % IMGW; }
    const int ppos = (oy + 1) * PW + (ox + 1);
    const int pair0 = branch * 16 + 2 * n;
    store_y_pair(pair0,     ppos, ax * invl, ay * invl);
    store_y_pair(pair0 + 1, ppos, az * invl, aw * invl);
}

// ---------------------------------------------------------------------------
// Branch 2, pass 1: row attention (fp32 out to g_v1).
// ---------------------------------------------------------------------------
__global__ __launch_bounds__(256) void axial_row_kernel(const float* __restrict__ lrls) {
    const int n = blockIdx.x / IMGW, h = blockIdx.x % IMGW;
    const int t = threadIdx.x;
    __shared__ float4 s_k[240], s_v[240];
    __shared__ float s_sc;
    if (t == 0) s_sc = expf(fminf(lrls[n], LOG_MAX));

    if (t < 240) {
        const int pos = h * IMGW + t;
        float4 kk, vv;
        kk.x = g_conv1[(128 + n * 4 + 0) * HW + pos];
        kk.y = g_conv1[(128 + n * 4 + 1) * HW + pos];
        kk.z = g_conv1[(128 + n * 4 + 2) * HW + pos];
        kk.w = g_conv1[(128 + n * 4 + 3) * HW + pos];
        vv.x = g_conv1[(160 + n * 4 + 0) * HW + pos];
        vv.y = g_conv1[(160 + n * 4 + 1) * HW + pos];
        vv.z = g_conv1[(160 + n * 4 + 2) * HW + pos];
        vv.w = g_conv1[(160 + n * 4 + 3) * HW + pos];
        s_k[t] = l2n(kk);
        s_v[t] = vv;
    }
    __syncthreads();
    if (t >= 240) return;

    const int pos = h * IMGW + t;
    float4 q;
    q.x = g_conv1[(256 + n * 4 + 0) * HW + pos];
    q.y = g_conv1[(256 + n * 4 + 1) * HW + pos];
    q.z = g_conv1[(256 + n * 4 + 2) * HW + pos];
    q.w = g_conv1[(256 + n * 4 + 3) * HW + pos];
    q = l2n(q);
    const float sc = s_sc;

    float l = 0.f, ax = 0, ay = 0, az = 0, aw = 0;
#pragma unroll 4
    for (int j = 0; j < 240; j++) {
        float4 kj = s_k[j];
        float s = sc * (q.x * kj.x + q.y * kj.y + q.z * kj.z + q.w * kj.w);
        float wgt = __expf(s - sc);
        float4 vj = s_v[j];
        l += wgt;
        ax += wgt * vj.x; ay += wgt * vj.y; az += wgt * vj.z; aw += wgt * vj.w;
    }
    float invl = 1.f / l;
    g_v1[(n * 4 + 0) * HW + pos] = ax * invl;
    g_v1[(n * 4 + 1) * HW + pos] = ay * invl;
    g_v1[(n * 4 + 2) * HW + pos] = az * invl;
    g_v1[(n * 4 + 3) * HW + pos] = aw * invl;
}

// ---------------------------------------------------------------------------
// Branch 2, pass 2: column attention -> packed padded y (pairs 32..47).
// ---------------------------------------------------------------------------
__global__ __launch_bounds__(256) void axial_col_kernel(const float* __restrict__ lrls) {
    const int n = blockIdx.x / IMGW, w = blockIdx.x % IMGW;
    const int t = threadIdx.x;
    __shared__ float4 s_k[240], s_v[240];
    __shared__ float s_sc;
    if (t == 0) s_sc = expf(fminf(lrls[n], LOG_MAX));

    if (t < 240) {
        const int pos = t * IMGW + w;
        float4 kk, vv;
        kk.x = g_conv1[(128 + n * 4 + 0) * HW + pos];
        kk.y = g_conv1[(128 + n * 4 + 1) * HW + pos];
        kk.z = g_conv1[(128 + n * 4 + 2) * HW + pos];
        kk.w = g_conv1[(128 + n * 4 + 3) * HW + pos];
        vv.x = g_v1[(n * 4 + 0) * HW + pos];
        vv.y = g_v1[(n * 4 + 1) * HW + pos];
        vv.z = g_v1[(n * 4 + 2) * HW + pos];
        vv.w = g_v1[(n * 4 + 3) * HW + pos];
        s_k[t] = l2n(kk);
        s_v[t] = vv;
    }
    __syncthreads();
    if (t >= 240) return;

    const int pos = t * IMGW + w;
    float4 q;
    q.x = g_conv1[(256 + n * 4 + 0) * HW + pos];
    q.y = g_conv1[(256 + n * 4 + 1) * HW + pos];
    q.z = g_conv1[(256 + n * 4 + 2) * HW + pos];
    q.w = g_conv1[(256 + n * 4 + 3) * HW + pos];
    q = l2n(q);
    const float sc = s_sc;

    float l = 0.f, ax = 0, ay = 0, az = 0, aw = 0;
#pragma unroll 4
    for (int j = 0; j < 240; j++) {
        float4 kj = s_k[j];
        float s = sc * (q.x * kj.x + q.y * kj.y + q.z * kj.z + q.w * kj.w);
        float wgt = __expf(s - sc);
        float4 vj = s_v[j];
        l += wgt;
        ax += wgt * vj.x; ay += wgt * vj.y; az += wgt * vj.z; aw += wgt * vj.w;
    }
    float invl = 1.f / l;
    const int ppos = (t + 1) * PW + (w + 1);
    const int pair0 = 32 + 2 * n;
    store_y_pair(pair0,     ppos, ax * invl, ay * invl);
    store_y_pair(pair0 + 1, ppos, az * invl, aw * invl);
}

// ---------------------------------------------------------------------------
extern "C" void kernel_launch(void* const* d_in, const int* in_sizes, int n_in,
                              void* d_out, int out_size) {
    const float* x      = (const float*)d_in[0];
    const float* w_in   = (const float*)d_in[1];
    const float* b_in   = (const float*)d_in[2];
    const float* w_f    = (const float*)d_in[3];
    const float* b_f    = (const float*)d_in[4];
    const float* w_out  = (const float*)d_in[5];
    const float* b_out  = (const float*)d_in[6];
    const float* ls     = (const float*)d_in[7];
    const float* lr_ls  = (const float*)d_in[8];
    float* out = (float*)d_out;

    float* p_conv1; unsigned* p_wrep; float* p_bias;
    unsigned *p_xh, *p_xl, *p_yh, *p_yl;
    cudaGetSymbolAddress((void**)&p_conv1, g_conv1);
    cudaGetSymbolAddress((void**)&p_wrep, g_wrep);
    cudaGetSymbolAddress((void**)&p_bias, g_bias);
    cudaGetSymbolAddress((void**)&p_xh, g_xa_hi);
    cudaGetSymbolAddress((void**)&p_xl, g_xa_lo);
    cudaGetSymbolAddress((void**)&p_yh, g_ya_hi);
    cudaGetSymbolAddress((void**)&p_yl, g_ya_lo);

    const int SMEM_BYTES = 20224 * 4;  // 80896
    static int attr_set = 0;
    if (!attr_set) {
        cudaFuncSetAttribute(conv3x3_mma_kernel,
                             cudaFuncAttributeMaxDynamicSharedMemorySize, SMEM_BYTES);
        attr_set = 1;
    }

    // prep: padded bf16 input, y borders, weights, bias
    prep_x_kernel<<<(48 * PHW + 255) / 256, 256>>>(x);
    zero_yborder_kernel<<<(48 * 1448 + 255) / 256, 256>>>();
    unsigned* wrep_out = p_wrep + 2 * 288 * 432;
    repack_w_kernel<<<(192 * 432 + 255) / 256, 256>>>(w_in, p_wrep, 192, 0, 288);
    repack_w_kernel<<<(96 * 432 + 255) / 256, 256>>>(w_f, p_wrep, 96, 192, 288);
    repack_w_kernel<<<(96 * 432 + 255) / 256, 256>>>(w_out, wrep_out, 96, 0, 96);
    bias_combine_kernel<<<1, 288>>>(b_in, b_f);

    // fused conv_in + conv_f (288 oc) -> g_conv1 fp32
    conv3x3_mma_kernel<<<dim3(15, 30, 3), 256, SMEM_BYTES>>>(p_xh, p_xl, p_wrep,
                                                             p_bias, p_conv1, 288);

    win_attn_kernel<<<dim3(2304, 2), 256>>>(ls);
    axial_row_kernel<<<8 * IMGW, 256>>>(lr_ls);
    axial_col_kernel<<<8 * IMGW, 256>>>(lr_ls);

    // output conv reads packed padded y
    conv3x3_mma_kernel<<<dim3(15, 30, 1), 256, SMEM_BYTES>>>(p_yh, p_yl, wrep_out,
                                                             b_out, out, 96);
}

// round 7
// speedup vs baseline: 4.2895x; 1.0278x over previous
#include <cuda_runtime.h>
#include <cuda_bf16.h>
#include <math.h>

#define HW    57600
#define IMGW  240
#define PW    244
#define PH    242
#define PHW   (PH * PW)      // 59048
#define LOG_MAX 4.6051701859880914f

// Scratch (allocation-free):
__device__ float    g_conv1[288 * HW];
__device__ float    g_v1[32 * HW];
__device__ unsigned g_wrep[768 * 864];
__device__ float    g_bias[288];
__device__ unsigned g_xa_hi[48 * PHW];
__device__ unsigned g_xa_lo[48 * PHW];
__device__ unsigned g_ya_hi[48 * PHW];
__device__ unsigned g_ya_lo[48 * PHW];

__device__ __forceinline__ unsigned pack_bf2(float a, float b) {
    __nv_bfloat162 h;
    h.x = __float2bfloat16_rn(a);
    h.y = __float2bfloat16_rn(b);
    return *(unsigned*)&h;
}
__device__ __forceinline__ unsigned smem_u32(const void* p) {
    return (unsigned)__cvta_generic_to_shared(p);
}
#define CP16(dst, src) asm volatile("cp.async.cg.shared.global [%0], [%1], 16;" :: "r"(dst), "l"(src))
#define CP8(dst, src)  asm volatile("cp.async.ca.shared.global [%0], [%1], 8;"  :: "r"(dst), "l"(src))
#define CP_COMMIT()    asm volatile("cp.async.commit_group;" ::: "memory")
#define CP_WAIT_ALL()  asm volatile("cp.async.wait_group 0;" ::: "memory")

// ---------------------------------------------------------------------------
// Fused prep: pack x to padded bf16 hi/lo | zero y borders | combine bias.
// ---------------------------------------------------------------------------
#define NPREP_X (48 * PHW)
#define NPREP_B (48 * (2 * PW + 4 * 240))
__global__ void prep_all_kernel(const float* __restrict__ x,
                                const float* __restrict__ b_in,
                                const float* __restrict__ b_f) {
    int idx = blockIdx.x * 256 + threadIdx.x;
    if (idx < NPREP_X) {
        int p = idx / PHW, rem = idx % PHW;
        int py = rem / PW, px = rem % PW;
        float v0 = 0.f, v1 = 0.f;
        if (py >= 1 && py <= 240 && px >= 1 && px <= 240) {
            int pos = (py - 1) * IMGW + (px - 1);
            v0 = x[(2 * p) * HW + pos];
            v1 = x[(2 * p + 1) * HW + pos];
        }
        __nv_bfloat16 h0 = __float2bfloat16_rn(v0);
        __nv_bfloat16 h1 = __float2bfloat16_rn(v1);
        __nv_bfloat162 hh; hh.x = h0; hh.y = h1;
        g_xa_hi[idx] = *(unsigned*)&hh;
        g_xa_lo[idx] = pack_bf2(v0 - __bfloat162float(h0), v1 - __bfloat162float(h1));
        return;
    }
    idx -= NPREP_X;
    if (idx < NPREP_B) {
        const int PER = 2 * PW + 4 * 240;
        int p = idx / PER, j = idx % PER;
        int py, px;
        if (j < 2 * PW) { py = (j / PW) ? 241 : 0; px = j % PW; }
        else {
            int k = j - 2 * PW;
            py = 1 + (k % 240);
            int c = k / 240;
            px = (c == 0) ? 0 : 240 + c;
        }
        int o = p * PHW + py * PW + px;
        g_ya_hi[o] = 0u;
        g_ya_lo[o] = 0u;
        return;
    }
    idx -= NPREP_B;
    if (idx < 288)
        g_bias[idx] = idx < 192 ? b_in[idx] : b_f[idx - 192];
}

// ---------------------------------------------------------------------------
// Fused weight repack (w_in, w_f -> region0 Cout=288; w_out -> region1 Cout=96)
// layout per region: [chunk][shift][icpair][oc_global], hi array then lo array.
// ---------------------------------------------------------------------------
__device__ __forceinline__ void repack_one(const float* wt, unsigned* wrep,
                                           int idx, int CoutLocal, int ocOff,
                                           int CoutTotal) {
    int o = idx % CoutLocal;
    int rem = idx / CoutLocal;
    int p = rem % 8; int rem2 = rem / 8;
    int s = rem2 % 9;
    int ch = rem2 / 9;
    int ic = ch * 16 + 2 * p;
    float v0 = wt[(o * 96 + ic) * 9 + s];
    float v1 = wt[(o * 96 + ic + 1) * 9 + s];
    __nv_bfloat16 h0 = __float2bfloat16_rn(v0);
    __nv_bfloat16 h1 = __float2bfloat16_rn(v1);
    __nv_bfloat162 hi; hi.x = h0; hi.y = h1;
    int dst = rem * CoutTotal + ocOff + o;
    wrep[dst] = *(unsigned*)&hi;
    wrep[CoutTotal * 432 + dst] =
        pack_bf2(v0 - __bfloat162float(h0), v1 - __bfloat162float(h1));
}

__global__ void repack_all_kernel(const float* __restrict__ w_in,
                                  const float* __restrict__ w_f,
                                  const float* __restrict__ w_out) {
    int idx = blockIdx.x * 256 + threadIdx.x;
    const int T1 = 192 * 432, T2 = 96 * 432;
    if (idx < T1) { repack_one(w_in, g_wrep, idx, 192, 0, 288); return; }
    idx -= T1;
    if (idx < T2) { repack_one(w_f, g_wrep, idx, 96, 192, 288); return; }
    idx -= T2;
    if (idx < T2) repack_one(w_out, g_wrep + 2 * 288 * 432, idx, 96, 0, 96);
}

// ---------------------------------------------------------------------------
// Implicit-GEMM 3x3 conv, m16n8k16 bf16, 2-way split, cp.async pipelined.
// ---------------------------------------------------------------------------
__global__ __launch_bounds__(256, 2) void conv3x3_mma_kernel(
    const unsigned* __restrict__ in_hi, const unsigned* __restrict__ in_lo,
    const unsigned* __restrict__ wrep, const float* __restrict__ bias,
    float* __restrict__ out, int Cout) {
    extern __shared__ unsigned smem[];
    unsigned* s_b_hi = smem + 6400;
    unsigned* s_b_lo = smem + 13312;

    const int tid = threadIdx.x;
    const int lane = tid & 31, w = tid >> 5;
    const int wm = w & 1, wn = w >> 1;
    const int x0 = blockIdx.x * 16, y0 = blockIdx.y * 8;
    const int oc_blk = blockIdx.z * 96;
    const int g = lane >> 2, t = lane & 3;
    const int wlo = Cout * 432;

    auto stage_a = [&](int ch, int buf) {
        unsigned* a_base = smem + buf * 3200;
        for (int i = tid; i < 800; i += 256) {
            int p = i / 100, r = i % 100;
            int ly = r / 10, seg = r % 10;
            int is_lo = seg >= 5, s5 = seg - is_lo * 5;
            int lx = s5 * 4;
            const unsigned* src = (is_lo ? in_lo : in_hi) +
                                  (ch * 8 + p) * PHW + (y0 + ly) * PW + x0 + lx;
            unsigned dst = smem_u32(a_base + is_lo * 1600 + p * 200 + ly * 20 + lx);
            if (s5 < 4) CP16(dst, src);
            else        CP8(dst, src);
        }
    };
    auto stage_b = [&](int ch) {
        for (int i = tid; i < 3456; i += 256) {
            int is_lo = i >= 1728, k = i - is_lo * 1728;
            int r = k / 24, c = k % 24;
            const unsigned* src = wrep + is_lo * wlo +
                                  (ch * 72 + r) * Cout + oc_blk + c * 4;
            int col = (c * 4) ^ ((r & 3) * 8);
            unsigned dst = smem_u32((is_lo ? s_b_lo : s_b_hi) + r * 96 + col);
            CP16(dst, src);
        }
    };

    float acc[4][3][4];
#pragma unroll
    for (int j = 0; j < 3; j++) {
        int oc = oc_blk + wn * 24 + j * 8 + 2 * t;
        float b0 = bias[oc], b1 = bias[oc + 1];
#pragma unroll
        for (int i = 0; i < 4; i++) {
            acc[i][j][0] = b0; acc[i][j][1] = b1;
            acc[i][j][2] = b0; acc[i][j][3] = b1;
        }
    }

    stage_a(0, 0);
    stage_b(0);
    CP_COMMIT();
    CP_WAIT_ALL();
    __syncthreads();

    for (int ch = 0; ch < 6; ch++) {
        if (ch < 5) { stage_a(ch + 1, (ch + 1) & 1); CP_COMMIT(); }

        const unsigned* a_hi = smem + (ch & 1) * 3200;
        const unsigned* a_lo = a_hi + 1600;

#pragma unroll 3
        for (int s = 0; s < 9; s++) {
            const int dy = s / 3, dx = s % 3;
            unsigned bh[3][2], bl[3][2];
            const int swz = t * 8;
#pragma unroll
            for (int j = 0; j < 3; j++) {
                int oc = (wn * 24 + j * 8 + g) ^ swz;
                bh[j][0] = s_b_hi[(s * 8 + t) * 96 + oc];
                bh[j][1] = s_b_hi[(s * 8 + t + 4) * 96 + oc];
                bl[j][0] = s_b_lo[(s * 8 + t) * 96 + oc];
                bl[j][1] = s_b_lo[(s * 8 + t + 4) * 96 + oc];
            }
#pragma unroll
            for (int i = 0; i < 4; i++) {
                int py = wm * 4 + i;
                int o00 = t * 200 + (py + dy) * 20 + g + dx;
                int o4  = o00 + 800;
                unsigned ah0 = a_hi[o00], ah1 = a_hi[o00 + 8];
                unsigned ah2 = a_hi[o4],  ah3 = a_hi[o4 + 8];
                unsigned al0 = a_lo[o00], al1 = a_lo[o00 + 8];
                unsigned al2 = a_lo[o4],  al3 = a_lo[o4 + 8];
#pragma unroll
                for (int j = 0; j < 3; j++) {
                    asm volatile(
                        "mma.sync.aligned.m16n8k16.row.col.f32.bf16.bf16.f32 "
                        "{%0,%1,%2,%3}, {%4,%5,%6,%7}, {%8,%9}, {%0,%1,%2,%3};"
                        : "+f"(acc[i][j][0]), "+f"(acc[i][j][1]),
                          "+f"(acc[i][j][2]), "+f"(acc[i][j][3])
                        : "r"(al0), "r"(al1), "r"(al2), "r"(al3),
                          "r"(bh[j][0]), "r"(bh[j][1]));
                    asm volatile(
                        "mma.sync.aligned.m16n8k16.row.col.f32.bf16.bf16.f32 "
                        "{%0,%1,%2,%3}, {%4,%5,%6,%7}, {%8,%9}, {%0,%1,%2,%3};"
                        : "+f"(acc[i][j][0]), "+f"(acc[i][j][1]),
                          "+f"(acc[i][j][2]), "+f"(acc[i][j][3])
                        : "r"(ah0), "r"(ah1), "r"(ah2), "r"(ah3),
                          "r"(bl[j][0]), "r"(bl[j][1]));
                    asm volatile(
                        "mma.sync.aligned.m16n8k16.row.col.f32.bf16.bf16.f32 "
                        "{%0,%1,%2,%3}, {%4,%5,%6,%7}, {%8,%9}, {%0,%1,%2,%3};"
                        : "+f"(acc[i][j][0]), "+f"(acc[i][j][1]),
                          "+f"(acc[i][j][2]), "+f"(acc[i][j][3])
                        : "r"(ah0), "r"(ah1), "r"(ah2), "r"(ah3),
                          "r"(bh[j][0]), "r"(bh[j][1]));
                }
            }
        }
        __syncthreads();
        if (ch < 5) {
            stage_b(ch + 1);
            CP_COMMIT();
            CP_WAIT_ALL();
            __syncthreads();
        }
    }

    const int gx0 = x0 + g;
#pragma unroll
    for (int i = 0; i < 4; i++) {
        int gy = y0 + wm * 4 + i;
#pragma unroll
        for (int j = 0; j < 3; j++) {
            int oc = oc_blk + wn * 24 + j * 8 + 2 * t;
            out[oc * HW + gy * IMGW + gx0] = acc[i][j][0];
            out[(oc + 1) * HW + gy * IMGW + gx0] = acc[i][j][1];
            out[oc * HW + gy * IMGW + gx0 + 8] = acc[i][j][2];
            out[(oc + 1) * HW + gy * IMGW + gx0 + 8] = acc[i][j][3];
        }
    }
}

__device__ __forceinline__ float4 l2n(float4 a) {
    float n = sqrtf(a.x * a.x + a.y * a.y + a.z * a.z + a.w * a.w);
    float inv = 1.f / fmaxf(n, 1e-12f);
    a.x *= inv; a.y *= inv; a.z *= inv; a.w *= inv;
    return a;
}

__device__ __forceinline__ void store_y_pair(int pair, int ppos, float a, float b) {
    __nv_bfloat16 ha = __float2bfloat16_rn(a), hb = __float2bfloat16_rn(b);
    __nv_bfloat162 hh; hh.x = ha; hh.y = hb;
    g_ya_hi[pair * PHW + ppos] = *(unsigned*)&hh;
    g_ya_lo[pair * PHW + ppos] =
        pack_bf2(a - __bfloat162float(ha), b - __bfloat162float(hb));
}

// ---------------------------------------------------------------------------
// Fused attention launch #1: window attention (branches 0,1; blocks [0,4608))
// and axial row attention (blocks [4608,6528)). Unshifted softmax (exp(s)):
// the e^{-sc} factor cancels in normalization; sc = exp(min(ls,LOG_MAX)) ~ 10.
// q is pre-scaled by sc so the inner loop is dot+exp+5 FMA.
// ---------------------------------------------------------------------------
__global__ __launch_bounds__(256) void attn_winrow_kernel(
    const float* __restrict__ ls, const float* __restrict__ lrls) {
    __shared__ float4 s_kv[480];   // win: k[0..199], v[200..399]; axial: k[0..239], v[240..479]
    __shared__ float s_sc[8];
    const int bx = blockIdx.x;
    const int t = threadIdx.x;

    if (bx < 4608) {
        // ---- window attention ----
        const int branch = bx / 2304;
        const int win = bx - branch * 2304;
        const int Hw = win / 48, Ww = win % 48;
        if (t < 8) s_sc[t] = expf(fminf(ls[t], LOG_MAX));

        const int n = t / 25, tok = t % 25;
        const int wy = tok / 5, wx = tok % 5;
        const int py = Hw * 5 + wy, px = Ww * 5 + wx;
        int gy = py, gx = px;
        if (branch) { gy = (gy + 3) % IMGW; gx = (gx + 3) % IMGW; }
        const int pos = gy * IMGW + gx;

        if (t < 200) {
            const float* xb = g_conv1 + branch * 64 * HW;
            float4 kk, vv;
            kk.x = xb[(n * 4 + 0) * HW + pos];
            kk.y = xb[(n * 4 + 1) * HW + pos];
            kk.z = xb[(n * 4 + 2) * HW + pos];
            kk.w = xb[(n * 4 + 3) * HW + pos];
            vv.x = xb[(32 + n * 4 + 0) * HW + pos];
            vv.y = xb[(32 + n * 4 + 1) * HW + pos];
            vv.z = xb[(32 + n * 4 + 2) * HW + pos];
            vv.w = xb[(32 + n * 4 + 3) * HW + pos];
            s_kv[n * 25 + tok] = l2n(kk);
            s_kv[200 + n * 25 + tok] = vv;
        }
        __syncthreads();
        if (t >= 200) return;

        const float* fb = g_conv1 + (192 + branch * 32) * HW;
        float4 q;
        q.x = fb[(n * 4 + 0) * HW + pos];
        q.y = fb[(n * 4 + 1) * HW + pos];
        q.z = fb[(n * 4 + 2) * HW + pos];
        q.w = fb[(n * 4 + 3) * HW + pos];
        q = l2n(q);
        const float sc = s_sc[n];
        q.x *= sc; q.y *= sc; q.z *= sc; q.w *= sc;

        float l = 0.f, ax = 0, ay = 0, az = 0, aw = 0;
#pragma unroll
        for (int j = 0; j < 25; j++) {
            float4 kj = s_kv[n * 25 + j];
            float s = q.x * kj.x + q.y * kj.y + q.z * kj.z + q.w * kj.w;
            float wgt = __expf(s);
            float4 vj = s_kv[200 + n * 25 + j];
            l += wgt;
            ax += wgt * vj.x; ay += wgt * vj.y; az += wgt * vj.z; aw += wgt * vj.w;
        }
        float invl = 1.f / l;

        int oy = py, ox = px;
        if (branch) { oy = (oy + 2) % IMGW; ox = (ox + 2) % IMGW; }
        const int ppos = (oy + 1) * PW + (ox + 1);
        const int pair0 = branch * 16 + 2 * n;
        store_y_pair(pair0,     ppos, ax * invl, ay * invl);
        store_y_pair(pair0 + 1, ppos, az * invl, aw * invl);
        return;
    }

    // ---- axial row attention ----
    const int id = bx - 4608;
    const int n = id / IMGW, h = id % IMGW;
    if (t == 0) s_sc[0] = expf(fminf(lrls[n], LOG_MAX));

    if (t < 240) {
        const int pos = h * IMGW + t;
        float4 kk, vv;
        kk.x = g_conv1[(128 + n * 4 + 0) * HW + pos];
        kk.y = g_conv1[(128 + n * 4 + 1) * HW + pos];
        kk.z = g_conv1[(128 + n * 4 + 2) * HW + pos];
        kk.w = g_conv1[(128 + n * 4 + 3) * HW + pos];
        vv.x = g_conv1[(160 + n * 4 + 0) * HW + pos];
        vv.y = g_conv1[(160 + n * 4 + 1) * HW + pos];
        vv.z = g_conv1[(160 + n * 4 + 2) * HW + pos];
        vv.w = g_conv1[(160 + n * 4 + 3) * HW + pos];
        s_kv[t] = l2n(kk);
        s_kv[240 + t] = vv;
    }
    __syncthreads();
    if (t >= 240) return;

    const int pos = h * IMGW + t;
    float4 q;
    q.x = g_conv1[(256 + n * 4 + 0) * HW + pos];
    q.y = g_conv1[(256 + n * 4 + 1) * HW + pos];
    q.z = g_conv1[(256 + n * 4 + 2) * HW + pos];
    q.w = g_conv1[(256 + n * 4 + 3) * HW + pos];
    q = l2n(q);
    const float sc = s_sc[0];
    q.x *= sc; q.y *= sc; q.z *= sc; q.w *= sc;

    float l = 0.f, ax = 0, ay = 0, az = 0, aw = 0;
#pragma unroll 4
    for (int j = 0; j < 240; j++) {
        float4 kj = s_kv[j];
        float s = q.x * kj.x + q.y * kj.y + q.z * kj.z + q.w * kj.w;
        float wgt = __expf(s);
        float4 vj = s_kv[240 + j];
        l += wgt;
        ax += wgt * vj.x; ay += wgt * vj.y; az += wgt * vj.z; aw += wgt * vj.w;
    }
    float invl = 1.f / l;
    g_v1[(n * 4 + 0) * HW + pos] = ax * invl;
    g_v1[(n * 4 + 1) * HW + pos] = ay * invl;
    g_v1[(n * 4 + 2) * HW + pos] = az * invl;
    g_v1[(n * 4 + 3) * HW + pos] = aw * invl;
}

// ---------------------------------------------------------------------------
// Axial column attention -> packed padded y (pairs 32..47). Unshifted softmax.
// ---------------------------------------------------------------------------
__global__ __launch_bounds__(256) void axial_col_kernel(const float* __restrict__ lrls) {
    const int n = blockIdx.x / IMGW, w = blockIdx.x % IMGW;
    const int t = threadIdx.x;
    __shared__ float4 s_k[240], s_v[240];
    __shared__ float s_sc;
    if (t == 0) s_sc = expf(fminf(lrls[n], LOG_MAX));

    if (t < 240) {
        const int pos = t * IMGW + w;
        float4 kk, vv;
        kk.x = g_conv1[(128 + n * 4 + 0) * HW + pos];
        kk.y = g_conv1[(128 + n * 4 + 1) * HW + pos];
        kk.z = g_conv1[(128 + n * 4 + 2) * HW + pos];
        kk.w = g_conv1[(128 + n * 4 + 3) * HW + pos];
        vv.x = g_v1[(n * 4 + 0) * HW + pos];
        vv.y = g_v1[(n * 4 + 1) * HW + pos];
        vv.z = g_v1[(n * 4 + 2) * HW + pos];
        vv.w = g_v1[(n * 4 + 3) * HW + pos];
        s_k[t] = l2n(kk);
        s_v[t] = vv;
    }
    __syncthreads();
    if (t >= 240) return;

    const int pos = t * IMGW + w;
    float4 q;
    q.x = g_conv1[(256 + n * 4 + 0) * HW + pos];
    q.y = g_conv1[(256 + n * 4 + 1) * HW + pos];
    q.z = g_conv1[(256 + n * 4 + 2) * HW + pos];
    q.w = g_conv1[(256 + n * 4 + 3) * HW + pos];
    q = l2n(q);
    const float sc = s_sc;
    q.x *= sc; q.y *= sc; q.z *= sc; q.w *= sc;

    float l = 0.f, ax = 0, ay = 0, az = 0, aw = 0;
#pragma unroll 4
    for (int j = 0; j < 240; j++) {
        float4 kj = s_k[j];
        float s = q.x * kj.x + q.y * kj.y + q.z * kj.z + q.w * kj.w;
        float wgt = __expf(s);
        float4 vj = s_v[j];
        l += wgt;
        ax += wgt * vj.x; ay += wgt * vj.y; az += wgt * vj.z; aw += wgt * vj.w;
    }
    float invl = 1.f / l;
    const int ppos = (t + 1) * PW + (w + 1);
    const int pair0 = 32 + 2 * n;
    store_y_pair(pair0,     ppos, ax * invl, ay * invl);
    store_y_pair(pair0 + 1, ppos, az * invl, aw * invl);
}

// ---------------------------------------------------------------------------
extern "C" void kernel_launch(void* const* d_in, const int* in_sizes, int n_in,
                              void* d_out, int out_size) {
    const float* x      = (const float*)d_in[0];
    const float* w_in   = (const float*)d_in[1];
    const float* b_in   = (const float*)d_in[2];
    const float* w_f    = (const float*)d_in[3];
    const float* b_f    = (const float*)d_in[4];
    const float* w_out  = (const float*)d_in[5];
    const float* b_out  = (const float*)d_in[6];
    const float* ls     = (const float*)d_in[7];
    const float* lr_ls  = (const float*)d_in[8];
    float* out = (float*)d_out;

    float* p_conv1; unsigned* p_wrep; float* p_bias;
    unsigned *p_xh, *p_xl, *p_yh, *p_yl;
    cudaGetSymbolAddress((void**)&p_conv1, g_conv1);
    cudaGetSymbolAddress((void**)&p_wrep, g_wrep);
    cudaGetSymbolAddress((void**)&p_bias, g_bias);
    cudaGetSymbolAddress((void**)&p_xh, g_xa_hi);
    cudaGetSymbolAddress((void**)&p_xl, g_xa_lo);
    cudaGetSymbolAddress((void**)&p_yh, g_ya_hi);
    cudaGetSymbolAddress((void**)&p_yl, g_ya_lo);

    const int SMEM_BYTES = 20224 * 4;
    static int attr_set = 0;
    if (!attr_set) {
        cudaFuncSetAttribute(conv3x3_mma_kernel,
                             cudaFuncAttributeMaxDynamicSharedMemorySize, SMEM_BYTES);
        attr_set = 1;
    }

    const int NPREP = NPREP_X + NPREP_B + 288;
    prep_all_kernel<<<(NPREP + 255) / 256, 256>>>(x, b_in, b_f);
    repack_all_kernel<<<(384 * 432 + 255) / 256, 256>>>(w_in, w_f, w_out);

    conv3x3_mma_kernel<<<dim3(15, 30, 3), 256, SMEM_BYTES>>>(p_xh, p_xl, p_wrep,
                                                             p_bias, p_conv1, 288);

    attn_winrow_kernel<<<4608 + 8 * IMGW, 256>>>(ls, lr_ls);
    axial_col_kernel<<<8 * IMGW, 256>>>(lr_ls);

    unsigned* wrep_out = p_wrep + 2 * 288 * 432;
    conv3x3_mma_kernel<<<dim3(15, 30, 1), 256, SMEM_BYTES>>>(p_yh, p_yl, wrep_out,
                                                             b_out, out, 96);
}

// round 8
// speedup vs baseline: 4.3048x; 1.0036x over previous
#include <cuda_runtime.h>
#include <cuda_bf16.h>
#include <math.h>

#define HW    57600
#define IMGW  240
#define PW    244
#define PH    242
#define PHW   (PH * PW)      // 59048
#define LOG_MAX 4.6051701859880914f

// Scratch (allocation-free):
__device__ float    g_conv1[288 * HW];
__device__ float    g_v1[32 * HW];
__device__ unsigned g_wrep[768 * 864];
__device__ float    g_bias[288];
__device__ unsigned g_xa_hi[48 * PHW];
__device__ unsigned g_xa_lo[48 * PHW];
__device__ unsigned g_ya_hi[48 * PHW];
__device__ unsigned g_ya_lo[48 * PHW];

__device__ __forceinline__ unsigned pack_bf2(float a, float b) {
    __nv_bfloat162 h;
    h.x = __float2bfloat16_rn(a);
    h.y = __float2bfloat16_rn(b);
    return *(unsigned*)&h;
}
__device__ __forceinline__ unsigned smem_u32(const void* p) {
    return (unsigned)__cvta_generic_to_shared(p);
}
#define CP16(dst, src) asm volatile("cp.async.cg.shared.global [%0], [%1], 16;" :: "r"(dst), "l"(src))
#define CP8(dst, src)  asm volatile("cp.async.ca.shared.global [%0], [%1], 8;"  :: "r"(dst), "l"(src))
#define CP_COMMIT()    asm volatile("cp.async.commit_group;" ::: "memory")
#define CP_WAIT2()     asm volatile("cp.async.wait_group 2;" ::: "memory")

// ---------------------------------------------------------------------------
// Fused prep: pack x to padded bf16 hi/lo | zero y borders | combine bias.
// ---------------------------------------------------------------------------
#define NPREP_X (48 * PHW)
#define NPREP_B (48 * (2 * PW + 4 * 240))
__global__ void prep_all_kernel(const float* __restrict__ x,
                                const float* __restrict__ b_in,
                                const float* __restrict__ b_f) {
    int idx = blockIdx.x * 256 + threadIdx.x;
    if (idx < NPREP_X) {
        int p = idx / PHW, rem = idx % PHW;
        int py = rem / PW, px = rem % PW;
        float v0 = 0.f, v1 = 0.f;
        if (py >= 1 && py <= 240 && px >= 1 && px <= 240) {
            int pos = (py - 1) * IMGW + (px - 1);
            v0 = x[(2 * p) * HW + pos];
            v1 = x[(2 * p + 1) * HW + pos];
        }
        __nv_bfloat16 h0 = __float2bfloat16_rn(v0);
        __nv_bfloat16 h1 = __float2bfloat16_rn(v1);
        __nv_bfloat162 hh; hh.x = h0; hh.y = h1;
        g_xa_hi[idx] = *(unsigned*)&hh;
        g_xa_lo[idx] = pack_bf2(v0 - __bfloat162float(h0), v1 - __bfloat162float(h1));
        return;
    }
    idx -= NPREP_X;
    if (idx < NPREP_B) {
        const int PER = 2 * PW + 4 * 240;
        int p = idx / PER, j = idx % PER;
        int py, px;
        if (j < 2 * PW) { py = (j / PW) ? 241 : 0; px = j % PW; }
        else {
            int k = j - 2 * PW;
            py = 1 + (k % 240);
            int c = k / 240;
            px = (c == 0) ? 0 : 240 + c;
        }
        int o = p * PHW + py * PW + px;
        g_ya_hi[o] = 0u;
        g_ya_lo[o] = 0u;
        return;
    }
    idx -= NPREP_B;
    if (idx < 288)
        g_bias[idx] = idx < 192 ? b_in[idx] : b_f[idx - 192];
}

// ---------------------------------------------------------------------------
// Fused weight repack.
// ---------------------------------------------------------------------------
__device__ __forceinline__ void repack_one(const float* wt, unsigned* wrep,
                                           int idx, int CoutLocal, int ocOff,
                                           int CoutTotal) {
    int o = idx % CoutLocal;
    int rem = idx / CoutLocal;
    int p = rem % 8; int rem2 = rem / 8;
    int s = rem2 % 9;
    int ch = rem2 / 9;
    int ic = ch * 16 + 2 * p;
    float v0 = wt[(o * 96 + ic) * 9 + s];
    float v1 = wt[(o * 96 + ic + 1) * 9 + s];
    __nv_bfloat16 h0 = __float2bfloat16_rn(v0);
    __nv_bfloat16 h1 = __float2bfloat16_rn(v1);
    __nv_bfloat162 hi; hi.x = h0; hi.y = h1;
    int dst = rem * CoutTotal + ocOff + o;
    wrep[dst] = *(unsigned*)&hi;
    wrep[CoutTotal * 432 + dst] =
        pack_bf2(v0 - __bfloat162float(h0), v1 - __bfloat162float(h1));
}

__global__ void repack_all_kernel(const float* __restrict__ w_in,
                                  const float* __restrict__ w_f,
                                  const float* __restrict__ w_out) {
    int idx = blockIdx.x * 256 + threadIdx.x;
    const int T1 = 192 * 432, T2 = 96 * 432;
    if (idx < T1) { repack_one(w_in, g_wrep, idx, 192, 0, 288); return; }
    idx -= T1;
    if (idx < T2) { repack_one(w_f, g_wrep, idx, 96, 192, 288); return; }
    idx -= T2;
    if (idx < T2) repack_one(w_out, g_wrep + 2 * 288 * 432, idx, 96, 0, 96);
}

// ---------------------------------------------------------------------------
// Implicit-GEMM 3x3 conv, m16n8k16 bf16, 2-way split. Fully pipelined:
// A double-buffered; B staged in shift-halves (s0-4: rows 0-39, s5-8: rows
// 40-71) so each half loads while the other computes. cp.async groups are
// committed unconditionally (empty groups at the tail) so wait_group 2 is
// uniform and always guarantees the operands for the upcoming phase.
// ---------------------------------------------------------------------------
__global__ __launch_bounds__(256, 2) void conv3x3_mma_kernel(
    const unsigned* __restrict__ in_hi, const unsigned* __restrict__ in_lo,
    const unsigned* __restrict__ wrep, const float* __restrict__ bias,
    float* __restrict__ out, int Cout) {
    extern __shared__ unsigned smem[];
    unsigned* s_b_hi = smem + 6400;
    unsigned* s_b_lo = smem + 13312;

    const int tid = threadIdx.x;
    const int lane = tid & 31, w = tid >> 5;
    const int wm = w & 1, wn = w >> 1;
    const int x0 = blockIdx.x * 16, y0 = blockIdx.y * 8;
    const int oc_blk = blockIdx.z * 96;
    const int g = lane >> 2, t = lane & 3;
    const int wlo = Cout * 432;

    auto stage_a = [&](int ch, int buf) {
        unsigned* a_base = smem + buf * 3200;
        for (int i = tid; i < 800; i += 256) {
            int p = i / 100, r = i % 100;
            int ly = r / 10, seg = r % 10;
            int is_lo = seg >= 5, s5 = seg - is_lo * 5;
            int lx = s5 * 4;
            const unsigned* src = (is_lo ? in_lo : in_hi) +
                                  (ch * 8 + p) * PHW + (y0 + ly) * PW + x0 + lx;
            unsigned dst = smem_u32(a_base + is_lo * 1600 + p * 200 + ly * 20 + lx);
            if (s5 < 4) CP16(dst, src);
            else        CP8(dst, src);
        }
    };
    auto stage_b_rows = [&](int ch, int r0, int nrows) {
        int half = nrows * 24;
        for (int i = tid; i < half * 2; i += 256) {
            int is_lo = i >= half, k = i - is_lo * half;
            int r = r0 + k / 24, c = k % 24;
            const unsigned* src = wrep + is_lo * wlo +
                                  (ch * 72 + r) * Cout + oc_blk + c * 4;
            int col = (c * 4) ^ ((r & 3) * 8);
            unsigned dst = smem_u32((is_lo ? s_b_lo : s_b_hi) + r * 96 + col);
            CP16(dst, src);
        }
    };

    float acc[4][3][4];
#pragma unroll
    for (int j = 0; j < 3; j++) {
        int oc = oc_blk + wn * 24 + j * 8 + 2 * t;
        float b0 = bias[oc], b1 = bias[oc + 1];
#pragma unroll
        for (int i = 0; i < 4; i++) {
            acc[i][j][0] = b0; acc[i][j][1] = b1;
            acc[i][j][2] = b0; acc[i][j][3] = b1;
        }
    }

    stage_a(0, 0);      CP_COMMIT();   // G: A(0)
    stage_b_rows(0, 0, 40);  CP_COMMIT();   // G: B0(0)
    stage_b_rows(0, 40, 32); CP_COMMIT();   // G: B1(0)

    const unsigned* a_hi;
    const unsigned* a_lo;
    auto compute_shift = [&](int s) {
        const int dy = s / 3, dx = s % 3;
        unsigned bh[3][2], bl[3][2];
        const int swz = t * 8;
#pragma unroll
        for (int j = 0; j < 3; j++) {
            int oc = (wn * 24 + j * 8 + g) ^ swz;
            bh[j][0] = s_b_hi[(s * 8 + t) * 96 + oc];
            bh[j][1] = s_b_hi[(s * 8 + t + 4) * 96 + oc];
            bl[j][0] = s_b_lo[(s * 8 + t) * 96 + oc];
            bl[j][1] = s_b_lo[(s * 8 + t + 4) * 96 + oc];
        }
#pragma unroll
        for (int i = 0; i < 4; i++) {
            int py = wm * 4 + i;
            int o00 = t * 200 + (py + dy) * 20 + g + dx;
            int o4  = o00 + 800;
            unsigned ah0 = a_hi[o00], ah1 = a_hi[o00 + 8];
            unsigned ah2 = a_hi[o4],  ah3 = a_hi[o4 + 8];
            unsigned al0 = a_lo[o00], al1 = a_lo[o00 + 8];
            unsigned al2 = a_lo[o4],  al3 = a_lo[o4 + 8];
#pragma unroll
            for (int j = 0; j < 3; j++) {
                asm volatile(
                    "mma.sync.aligned.m16n8k16.row.col.f32.bf16.bf16.f32 "
                    "{%0,%1,%2,%3}, {%4,%5,%6,%7}, {%8,%9}, {%0,%1,%2,%3};"
                    : "+f"(acc[i][j][0]), "+f"(acc[i][j][1]),
                      "+f"(acc[i][j][2]), "+f"(acc[i][j][3])
                    : "r"(al0), "r"(al1), "r"(al2), "r"(al3),
                      "r"(bh[j][0]), "r"(bh[j][1]));
                asm volatile(
                    "mma.sync.aligned.m16n8k16.row.col.f32.bf16.bf16.f32 "
                    "{%0,%1,%2,%3}, {%4,%5,%6,%7}, {%8,%9}, {%0,%1,%2,%3};"
                    : "+f"(acc[i][j][0]), "+f"(acc[i][j][1]),
                      "+f"(acc[i][j][2]), "+f"(acc[i][j][3])
                    : "r"(ah0), "r"(ah1), "r"(ah2), "r"(ah3),
                      "r"(bl[j][0]), "r"(bl[j][1]));
                asm volatile(
                    "mma.sync.aligned.m16n8k16.row.col.f32.bf16.bf16.f32 "
                    "{%0,%1,%2,%3}, {%4,%5,%6,%7}, {%8,%9}, {%0,%1,%2,%3};"
                    : "+f"(acc[i][j][0]), "+f"(acc[i][j][1]),
                      "+f"(acc[i][j][2]), "+f"(acc[i][j][3])
                    : "r"(ah0), "r"(ah1), "r"(ah2), "r"(ah3),
                      "r"(bh[j][0]), "r"(bh[j][1]));
            }
        }
    };

    for (int ch = 0; ch < 6; ch++) {
        if (ch < 5) stage_a(ch + 1, (ch + 1) & 1);
        CP_COMMIT();                 // (maybe empty) -> pending: B1(ch), A(ch+1)
        CP_WAIT2();                  // A(ch), B0(ch) ready
        __syncthreads();

        a_hi = smem + (ch & 1) * 3200;
        a_lo = a_hi + 1600;
#pragma unroll
        for (int s = 0; s < 5; s++) compute_shift(s);
        __syncthreads();             // B0 free

        if (ch < 5) stage_b_rows(ch + 1, 0, 40);
        CP_COMMIT();                 // pending: B1(ch), A(ch+1), B0(ch+1)
        CP_WAIT2();                  // B1(ch) ready
        __syncthreads();
#pragma unroll
        for (int s = 5; s < 9; s++) compute_shift(s);
        __syncthreads();             // B1 and A(ch) free

        if (ch < 5) stage_b_rows(ch + 1, 40, 32);
        CP_COMMIT();                 // pending: A(ch+1), B0(ch+1), B1(ch+1)
    }

    const int gx0 = x0 + g;
#pragma unroll
    for (int i = 0; i < 4; i++) {
        int gy = y0 + wm * 4 + i;
#pragma unroll
        for (int j = 0; j < 3; j++) {
            int oc = oc_blk + wn * 24 + j * 8 + 2 * t;
            out[oc * HW + gy * IMGW + gx0] = acc[i][j][0];
            out[(oc + 1) * HW + gy * IMGW + gx0] = acc[i][j][1];
            out[oc * HW + gy * IMGW + gx0 + 8] = acc[i][j][2];
            out[(oc + 1) * HW + gy * IMGW + gx0 + 8] = acc[i][j][3];
        }
    }
}

__device__ __forceinline__ float4 l2n(float4 a) {
    float n = sqrtf(a.x * a.x + a.y * a.y + a.z * a.z + a.w * a.w);
    float inv = 1.f / fmaxf(n, 1e-12f);
    a.x *= inv; a.y *= inv; a.z *= inv; a.w *= inv;
    return a;
}

__device__ __forceinline__ void store_y_pair(int pair, int ppos, float a, float b) {
    __nv_bfloat16 ha = __float2bfloat16_rn(a), hb = __float2bfloat16_rn(b);
    __nv_bfloat162 hh; hh.x = ha; hh.y = hb;
    g_ya_hi[pair * PHW + ppos] = *(unsigned*)&hh;
    g_ya_lo[pair * PHW + ppos] =
        pack_bf2(a - __bfloat162float(ha), b - __bfloat162float(hb));
}

// ---------------------------------------------------------------------------
// Fused attention launch #1: HEAVY axial-row blocks first (bx < 1920), then
// window attention blocks (branches 0,1). Unshifted softmax (factor cancels).
// ---------------------------------------------------------------------------
__global__ __launch_bounds__(256) void attn_winrow_kernel(
    const float* __restrict__ ls, const float* __restrict__ lrls) {
    __shared__ float4 s_kv[480];
    __shared__ float s_sc[8];
    const int bx = blockIdx.x;
    const int t = threadIdx.x;

    if (bx >= 1920) {
        // ---- window attention ----
        const int wb = bx - 1920;
        const int branch = wb / 2304;
        const int win = wb - branch * 2304;
        const int Hw = win / 48, Ww = win % 48;
        if (t < 8) s_sc[t] = expf(fminf(ls[t], LOG_MAX));

        const int n = t / 25, tok = t % 25;
        const int wy = tok / 5, wx = tok % 5;
        const int py = Hw * 5 + wy, px = Ww * 5 + wx;
        int gy = py, gx = px;
        if (branch) { gy = (gy + 3) % IMGW; gx = (gx + 3) % IMGW; }
        const int pos = gy * IMGW + gx;

        if (t < 200) {
            const float* xb = g_conv1 + branch * 64 * HW;
            float4 kk, vv;
            kk.x = xb[(n * 4 + 0) * HW + pos];
            kk.y = xb[(n * 4 + 1) * HW + pos];
            kk.z = xb[(n * 4 + 2) * HW + pos];
            kk.w = xb[(n * 4 + 3) * HW + pos];
            vv.x = xb[(32 + n * 4 + 0) * HW + pos];
            vv.y = xb[(32 + n * 4 + 1) * HW + pos];
            vv.z = xb[(32 + n * 4 + 2) * HW + pos];
            vv.w = xb[(32 + n * 4 + 3) * HW + pos];
            s_kv[n * 25 + tok] = l2n(kk);
            s_kv[200 + n * 25 + tok] = vv;
        }
        __syncthreads();
        if (t >= 200) return;

        const float* fb = g_conv1 + (192 + branch * 32) * HW;
        float4 q;
        q.x = fb[(n * 4 + 0) * HW + pos];
        q.y = fb[(n * 4 + 1) * HW + pos];
        q.z = fb[(n * 4 + 2) * HW + pos];
        q.w = fb[(n * 4 + 3) * HW + pos];
        q = l2n(q);
        const float sc = s_sc[n];
        q.x *= sc; q.y *= sc; q.z *= sc; q.w *= sc;

        float l = 0.f, ax = 0, ay = 0, az = 0, aw = 0;
#pragma unroll
        for (int j = 0; j < 25; j++) {
            float4 kj = s_kv[n * 25 + j];
            float s = q.x * kj.x + q.y * kj.y + q.z * kj.z + q.w * kj.w;
            float wgt = __expf(s);
            float4 vj = s_kv[200 + n * 25 + j];
            l += wgt;
            ax += wgt * vj.x; ay += wgt * vj.y; az += wgt * vj.z; aw += wgt * vj.w;
        }
        float invl = 1.f / l;

        int oy = py, ox = px;
        if (branch) { oy = (oy + 2) % IMGW; ox = (ox + 2) % IMGW; }
        const int ppos = (oy + 1) * PW + (ox + 1);
        const int pair0 = branch * 16 + 2 * n;
        store_y_pair(pair0,     ppos, ax * invl, ay * invl);
        store_y_pair(pair0 + 1, ppos, az * invl, aw * invl);
        return;
    }

    // ---- axial row attention (heavy; scheduled first) ----
    const int n = bx / IMGW, h = bx % IMGW;
    if (t == 0) s_sc[0] = expf(fminf(lrls[n], LOG_MAX));

    if (t < 240) {
        const int pos = h * IMGW + t;
        float4 kk, vv;
        kk.x = g_conv1[(128 + n * 4 + 0) * HW + pos];
        kk.y = g_conv1[(128 + n * 4 + 1) * HW + pos];
        kk.z = g_conv1[(128 + n * 4 + 2) * HW + pos];
        kk.w = g_conv1[(128 + n * 4 + 3) * HW + pos];
        vv.x = g_conv1[(160 + n * 4 + 0) * HW + pos];
        vv.y = g_conv1[(160 + n * 4 + 1) * HW + pos];
        vv.z = g_conv1[(160 + n * 4 + 2) * HW + pos];
        vv.w = g_conv1[(160 + n * 4 + 3) * HW + pos];
        s_kv[t] = l2n(kk);
        s_kv[240 + t] = vv;
    }
    __syncthreads();
    if (t >= 240) return;

    const int pos = h * IMGW + t;
    float4 q;
    q.x = g_conv1[(256 + n * 4 + 0) * HW + pos];
    q.y = g_conv1[(256 + n * 4 + 1) * HW + pos];
    q.z = g_conv1[(256 + n * 4 + 2) * HW + pos];
    q.w = g_conv1[(256 + n * 4 + 3) * HW + pos];
    q = l2n(q);
    const float sc = s_sc[0];
    q.x *= sc; q.y *= sc; q.z *= sc; q.w *= sc;

    float l = 0.f, ax = 0, ay = 0, az = 0, aw = 0;
#pragma unroll 4
    for (int j = 0; j < 240; j++) {
        float4 kj = s_kv[j];
        float s = q.x * kj.x + q.y * kj.y + q.z * kj.z + q.w * kj.w;
        float wgt = __expf(s);
        float4 vj = s_kv[240 + j];
        l += wgt;
        ax += wgt * vj.x; ay += wgt * vj.y; az += wgt * vj.z; aw += wgt * vj.w;
    }
    float invl = 1.f / l;
    g_v1[(n * 4 + 0) * HW + pos] = ax * invl;
    g_v1[(n * 4 + 1) * HW + pos] = ay * invl;
    g_v1[(n * 4 + 2) * HW + pos] = az * invl;
    g_v1[(n * 4 + 3) * HW + pos] = aw * invl;
}

// ---------------------------------------------------------------------------
// Axial column attention -> packed padded y (pairs 32..47).
// ---------------------------------------------------------------------------
__global__ __launch_bounds__(256) void axial_col_kernel(const float* __restrict__ lrls) {
    const int n = blockIdx.x / IMGW, w = blockIdx.x % IMGW;
    const int t = threadIdx.x;
    __shared__ float4 s_k[240], s_v[240];
    __shared__ float s_sc;
    if (t == 0) s_sc = expf(fminf(lrls[n], LOG_MAX));

    if (t < 240) {
        const int pos = t * IMGW + w;
        float4 kk, vv;
        kk.x = g_conv1[(128 + n * 4 + 0) * HW + pos];
        kk.y = g_conv1[(128 + n * 4 + 1) * HW + pos];
        kk.z = g_conv1[(128 + n * 4 + 2) * HW + pos];
        kk.w = g_conv1[(128 + n * 4 + 3) * HW + pos];
        vv.x = g_v1[(n * 4 + 0) * HW + pos];
        vv.y = g_v1[(n * 4 + 1) * HW + pos];
        vv.z = g_v1[(n * 4 + 2) * HW + pos];
        vv.w = g_v1[(n * 4 + 3) * HW + pos];
        s_k[t] = l2n(kk);
        s_v[t] = vv;
    }
    __syncthreads();
    if (t >= 240) return;

    const int pos = t * IMGW + w;
    float4 q;
    q.x = g_conv1[(256 + n * 4 + 0) * HW + pos];
    q.y = g_conv1[(256 + n * 4 + 1) * HW + pos];
    q.z = g_conv1[(256 + n * 4 + 2) * HW + pos];
    q.w = g_conv1[(256 + n * 4 + 3) * HW + pos];
    q = l2n(q);
    const float sc = s_sc;
    q.x *= sc; q.y *= sc; q.z *= sc; q.w *= sc;

    float l = 0.f, ax = 0, ay = 0, az = 0, aw = 0;
#pragma unroll 4
    for (int j = 0; j < 240; j++) {
        float4 kj = s_k[j];
        float s = q.x * kj.x + q.y * kj.y + q.z * kj.z + q.w * kj.w;
        float wgt = __expf(s);
        float4 vj = s_v[j];
        l += wgt;
        ax += wgt * vj.x; ay += wgt * vj.y; az += wgt * vj.z; aw += wgt * vj.w;
    }
    float invl = 1.f / l;
    const int ppos = (t + 1) * PW + (w + 1);
    const int pair0 = 32 + 2 * n;
    store_y_pair(pair0,     ppos, ax * invl, ay * invl);
    store_y_pair(pair0 + 1, ppos, az * invl, aw * invl);
}

// ---------------------------------------------------------------------------
extern "C" void kernel_launch(void* const* d_in, const int* in_sizes, int n_in,
                              void* d_out, int out_size) {
    const float* x      = (const float*)d_in[0];
    const float* w_in   = (const float*)d_in[1];
    const float* b_in   = (const float*)d_in[2];
    const float* w_f    = (const float*)d_in[3];
    const float* b_f    = (const float*)d_in[4];
    const float* w_out  = (const float*)d_in[5];
    const float* b_out  = (const float*)d_in[6];
    const float* ls     = (const float*)d_in[7];
    const float* lr_ls  = (const float*)d_in[8];
    float* out = (float*)d_out;

    float* p_conv1; unsigned* p_wrep; float* p_bias;
    unsigned *p_xh, *p_xl, *p_yh, *p_yl;
    cudaGetSymbolAddress((void**)&p_conv1, g_conv1);
    cudaGetSymbolAddress((void**)&p_wrep, g_wrep);
    cudaGetSymbolAddress((void**)&p_bias, g_bias);
    cudaGetSymbolAddress((void**)&p_xh, g_xa_hi);
    cudaGetSymbolAddress((void**)&p_xl, g_xa_lo);
    cudaGetSymbolAddress((void**)&p_yh, g_ya_hi);
    cudaGetSymbolAddress((void**)&p_yl, g_ya_lo);

    const int SMEM_BYTES = 20224 * 4;
    static int attr_set = 0;
    if (!attr_set) {
        cudaFuncSetAttribute(conv3x3_mma_kernel,
                             cudaFuncAttributeMaxDynamicSharedMemorySize, SMEM_BYTES);
        attr_set = 1;
    }

    const int NPREP = NPREP_X + NPREP_B + 288;
    prep_all_kernel<<<(NPREP + 255) / 256, 256>>>(x, b_in, b_f);
    repack_all_kernel<<<(384 * 432 + 255) / 256, 256>>>(w_in, w_f, w_out);

    conv3x3_mma_kernel<<<dim3(15, 30, 3), 256, SMEM_BYTES>>>(p_xh, p_xl, p_wrep,
                                                             p_bias, p_conv1, 288);

    attn_winrow_kernel<<<1920 + 4608, 256>>>(ls, lr_ls);
    axial_col_kernel<<<8 * IMGW, 256>>>(lr_ls);

    unsigned* wrep_out = p_wrep + 2 * 288 * 432;
    conv3x3_mma_kernel<<<dim3(15, 30, 1), 256, SMEM_BYTES>>>(p_yh, p_yl, wrep_out,
                                                             b_out, out, 96);
}